// round 10
// baseline (speedup 1.0000x reference)
#include <cuda_runtime.h>

// Problem constants (fixed by the reference setup)
#define BB 64
#define SS 1024
#define DD 32
#define HH 2
#define DH 16
#define VV 28
#define LOG2E 1.44269504088896340736f

#define NQ (BB * HH * SS * DH)

typedef unsigned long long u64;

// Scratch (no allocations allowed -> __device__ globals), 16B-aligned
__device__ __align__(16) float g_Q[NQ];
__device__ __align__(16) float g_K[NQ];
__device__ __align__(16) float g_V[NQ];
__device__ __align__(16) float g_O[NQ];
__device__ int   g_Lb[BB];
__device__ __align__(16) float g_wc[VV * DD];
__device__ float g_bc[VV];

// ---------------------------------------------------------------------------
// Packed f32x2 + misc PTX helpers
// ---------------------------------------------------------------------------
__device__ __forceinline__ u64 fma2(u64 a, u64 b, u64 c) {
    u64 d; asm("fma.rn.f32x2 %0,%1,%2,%3;" : "=l"(d) : "l"(a), "l"(b), "l"(c));
    return d;
}
__device__ __forceinline__ u64 mul2(u64 a, u64 b) {
    u64 d; asm("mul.rn.f32x2 %0,%1,%2;" : "=l"(d) : "l"(a), "l"(b));
    return d;
}
__device__ __forceinline__ u64 add2(u64 a, u64 b) {
    u64 d; asm("add.rn.f32x2 %0,%1,%2;" : "=l"(d) : "l"(a), "l"(b));
    return d;
}
__device__ __forceinline__ u64 pack2(float x, float y) {
    u64 r; asm("mov.b64 %0,{%1,%2};" : "=l"(r) : "f"(x), "f"(y));
    return r;
}
__device__ __forceinline__ float2 unpk(u64 v) {
    float2 r; asm("mov.b64 {%0,%1},%2;" : "=f"(r.x), "=f"(r.y) : "l"(v));
    return r;
}
__device__ __forceinline__ float ex2(float x) {
    float r; asm("ex2.approx.f32 %0,%1;" : "=f"(r) : "f"(x));
    return r;
}
__device__ __forceinline__ void cpa16(unsigned dst, const void* src) {
    asm volatile("cp.async.cg.shared.global [%0],[%1],16;" :: "r"(dst), "l"(src));
}
__device__ __forceinline__ void cpa_commit() {
    asm volatile("cp.async.commit_group;");
}
template<int N>
__device__ __forceinline__ void cpa_wait() {
    asm volatile("cp.async.wait_group %0;" :: "n"(N));
}

// ---------------------------------------------------------------------------
// K0: per-batch prefix length Lb + combined output weights wc = w_fc @ wo
// ---------------------------------------------------------------------------
__global__ void prep_kernel(const float* __restrict__ mask,
                            const float* __restrict__ wo,
                            const float* __restrict__ bo,
                            const float* __restrict__ wfc,
                            const float* __restrict__ bfc) {
    int tid = threadIdx.x;
    int bb  = blockIdx.x;
    if (bb < BB) {
        __shared__ int smax[256];
        int mx = -1;
        const float* mp = mask + bb * SS;
        for (int s = tid; s < SS; s += 256)
            if (mp[s] > 0.f) mx = max(mx, s);
        smax[tid] = mx;
        __syncthreads();
        for (int off = 128; off > 0; off >>= 1) {
            if (tid < off) smax[tid] = max(smax[tid], smax[tid + off]);
            __syncthreads();
        }
        if (tid == 0) g_Lb[bb] = min(smax[0] + 4, SS);
    } else {
        for (int e = tid; e < VV * DD; e += 256) {
            int v = e >> 5, d = e & 31;
            float acc = 0.f;
            #pragma unroll
            for (int t = 0; t < 32; t++)
                acc += wfc[v * 32 + t] * wo[t * 32 + d];
            g_wc[e] = acc;
        }
        if (tid < VV) {
            float acc = bfc[tid];
            #pragma unroll
            for (int t = 0; t < 32; t++)
                acc += wfc[tid * 32 + t] * bo[t];
            g_bc[tid] = acc;
        }
    }
}

// ---------------------------------------------------------------------------
// K1: QKV projections. Thread per token. Q pre-scaled by 0.25*log2(e) so the
//     attention kernel can use ex2 directly. Layout [B,H,S,DH].
// ---------------------------------------------------------------------------
__global__ void __launch_bounds__(256) qkv_kernel(
    const int* __restrict__ x,  const float* __restrict__ emb,
    const float* __restrict__ pe,
    const float* __restrict__ wq, const float* __restrict__ bq,
    const float* __restrict__ wk, const float* __restrict__ bk,
    const float* __restrict__ wv, const float* __restrict__ bv) {

    __shared__ __align__(16) float sw[3 * 1024 + 96];
    int tid = threadIdx.x;
    for (int i = tid; i < 1024; i += 256) {
        sw[i]        = wq[i];
        sw[1024 + i] = wk[i];
        sw[2048 + i] = wv[i];
    }
    if (tid < 32) {
        sw[3072 + tid] = bq[tid];
        sw[3104 + tid] = bk[tid];
        sw[3136 + tid] = bv[tid];
    }
    __syncthreads();

    int t = blockIdx.x * 256 + tid;
    int b = t >> 10, s = t & 1023;
    int Lb = g_Lb[b];
    const float QSCL = 0.25f * LOG2E;

    if (s >= Lb) {
        #pragma unroll
        for (int j = 0; j < 32; j++) {
            int head = j >> 4, dd = j & 15;
            g_Q[((b * HH + head) * SS + s) * DH + dd] = sw[3072 + j] * QSCL;
        }
        return;
    }

    int xid = x[t];
    u64 h2[16];
    const float4* ep = (const float4*)(emb + xid * 32);
    const float4* pp = (const float4*)(pe + s * 32);
    #pragma unroll
    for (int j = 0; j < 8; j++) {
        float4 e4 = ep[j], p4 = pp[j];
        h2[2 * j]     = pack2(e4.x + p4.x, e4.y + p4.y);
        h2[2 * j + 1] = pack2(e4.z + p4.z, e4.w + p4.w);
    }

    #pragma unroll
    for (int mtx = 0; mtx < 3; mtx++) {
        const float* w    = sw + mtx * 1024;
        const float* bias = sw + 3072 + mtx * 32;
        float* outp = (mtx == 0) ? g_Q : ((mtx == 1) ? g_K : g_V);
        float scl = (mtx == 0) ? QSCL : 1.0f;
        #pragma unroll 4
        for (int j = 0; j < 32; j++) {
            const ulonglong2* wr = (const ulonglong2*)(w + j * 32);
            ulonglong2 w0 = wr[0], w1 = wr[1], w2 = wr[2], w3 = wr[3];
            ulonglong2 w4 = wr[4], w5 = wr[5], w6 = wr[6], w7 = wr[7];
            u64 a0 = mul2(h2[0], w0.x);
            u64 a1 = mul2(h2[1], w0.y);
            a0 = fma2(h2[2],  w1.x, a0);  a1 = fma2(h2[3],  w1.y, a1);
            a0 = fma2(h2[4],  w2.x, a0);  a1 = fma2(h2[5],  w2.y, a1);
            a0 = fma2(h2[6],  w3.x, a0);  a1 = fma2(h2[7],  w3.y, a1);
            a0 = fma2(h2[8],  w4.x, a0);  a1 = fma2(h2[9],  w4.y, a1);
            a0 = fma2(h2[10], w5.x, a0);  a1 = fma2(h2[11], w5.y, a1);
            a0 = fma2(h2[12], w6.x, a0);  a1 = fma2(h2[13], w6.y, a1);
            a0 = fma2(h2[14], w7.x, a0);  a1 = fma2(h2[15], w7.y, a1);
            float2 p = unpk(add2(a0, a1));
            float r = (p.x + p.y + bias[j]) * scl;
            int head = j >> 4, dd = j & 15;
            outp[((b * HH + head) * SS + s) * DH + dd] = r;
        }
    }
}

// ---------------------------------------------------------------------------
// K2: attention. Block = 128 threads handles a 256-query tile (2 q/thread),
//     grid (B*H, 4). K/V tiles of 128 keys, cp.async double-buffered.
//     No-max softmax via ex2 (scores bounded ~|9|); q pre-scaled by log2e.
// ---------------------------------------------------------------------------
__device__ __forceinline__ void qk1(const ulonglong2* __restrict__ kp,
                                    const ulonglong2* __restrict__ vp,
                                    const u64 q[8], u64 o[8], float& l) {
    ulonglong2 k0 = kp[0], k1 = kp[1], k2 = kp[2], k3 = kp[3];
    u64 a = mul2(q[0], k0.x);
    a = fma2(q[1], k0.y, a);
    a = fma2(q[2], k1.x, a);  a = fma2(q[3], k1.y, a);
    a = fma2(q[4], k2.x, a);  a = fma2(q[5], k2.y, a);
    a = fma2(q[6], k3.x, a);  a = fma2(q[7], k3.y, a);
    float2 p = unpk(a);
    float e = ex2(p.x + p.y);
    l += e;
    u64 e2 = pack2(e, e);
    ulonglong2 v0 = vp[0], v1 = vp[1], v2 = vp[2], v3 = vp[3];
    o[0] = fma2(e2, v0.x, o[0]);  o[1] = fma2(e2, v0.y, o[1]);
    o[2] = fma2(e2, v1.x, o[2]);  o[3] = fma2(e2, v1.y, o[3]);
    o[4] = fma2(e2, v2.x, o[4]);  o[5] = fma2(e2, v2.y, o[5]);
    o[6] = fma2(e2, v3.x, o[6]);  o[7] = fma2(e2, v3.y, o[7]);
}

__device__ __forceinline__ void qk2(const u64* __restrict__ skv, int k,
                                    const u64 qa[8], const u64 qb[8],
                                    u64 oa[8], u64 ob[8],
                                    float& la, float& lb) {
    const ulonglong2* kp = (const ulonglong2*)(skv + (size_t)k * 8);
    const ulonglong2* vp = (const ulonglong2*)(skv + 1024 + (size_t)k * 8);
    ulonglong2 k0 = kp[0], k1 = kp[1], k2 = kp[2], k3 = kp[3];
    ulonglong2 v0 = vp[0], v1 = vp[1], v2 = vp[2], v3 = vp[3];

    u64 a = mul2(qa[0], k0.x);
    u64 b = mul2(qb[0], k0.x);
    a = fma2(qa[1], k0.y, a);  b = fma2(qb[1], k0.y, b);
    a = fma2(qa[2], k1.x, a);  b = fma2(qb[2], k1.x, b);
    a = fma2(qa[3], k1.y, a);  b = fma2(qb[3], k1.y, b);
    a = fma2(qa[4], k2.x, a);  b = fma2(qb[4], k2.x, b);
    a = fma2(qa[5], k2.y, a);  b = fma2(qb[5], k2.y, b);
    a = fma2(qa[6], k3.x, a);  b = fma2(qb[6], k3.x, b);
    a = fma2(qa[7], k3.y, a);  b = fma2(qb[7], k3.y, b);
    float2 pa = unpk(a), pb = unpk(b);
    float ea = ex2(pa.x + pa.y);
    float eb = ex2(pb.x + pb.y);
    la += ea;  lb += eb;
    u64 ea2 = pack2(ea, ea), eb2 = pack2(eb, eb);
    oa[0] = fma2(ea2, v0.x, oa[0]);  ob[0] = fma2(eb2, v0.x, ob[0]);
    oa[1] = fma2(ea2, v0.y, oa[1]);  ob[1] = fma2(eb2, v0.y, ob[1]);
    oa[2] = fma2(ea2, v1.x, oa[2]);  ob[2] = fma2(eb2, v1.x, ob[2]);
    oa[3] = fma2(ea2, v1.y, oa[3]);  ob[3] = fma2(eb2, v1.y, ob[3]);
    oa[4] = fma2(ea2, v2.x, oa[4]);  ob[4] = fma2(eb2, v2.x, ob[4]);
    oa[5] = fma2(ea2, v2.y, oa[5]);  ob[5] = fma2(eb2, v2.y, ob[5]);
    oa[6] = fma2(ea2, v3.x, oa[6]);  ob[6] = fma2(eb2, v3.x, ob[6]);
    oa[7] = fma2(ea2, v3.y, oa[7]);  ob[7] = fma2(eb2, v3.y, ob[7]);
}

__global__ void __launch_bounds__(128) attn_kernel() {
    // two stages, each: K tile 8KB + V tile 8KB  -> 32 KB total
    __shared__ __align__(16) u64 skv[2][2048];

    int bh  = blockIdx.x;
    int b   = bh >> 1;
    int q0  = blockIdx.y << 8;          // 256-query tile
    int tid = threadIdx.x;
    int Lb  = g_Lb[b];

    const char* Kc = (const char*)(g_K + (size_t)bh * SS * DH);
    const char* Vc = (const char*)(g_V + (size_t)bh * SS * DH);

    if (q0 < Lb) {
        // ----------------- normal mode: 2 queries per thread -----------------
        u64 qa[8], qb[8], oa[8], ob[8];
        const u64* Qpa = (const u64*)(g_Q + ((size_t)bh * SS + q0 + tid) * DH);
        const u64* Qpb = (const u64*)(g_Q + ((size_t)bh * SS + q0 + 128 + tid) * DH);
        #pragma unroll
        for (int j = 0; j < 8; j++) { qa[j] = Qpa[j]; qb[j] = Qpb[j]; }
        float la = 0.f, lb = 0.f;
        #pragma unroll
        for (int j = 0; j < 8; j++) { oa[j] = 0ull; ob[j] = 0ull; }

        int nt = (Lb + 127) >> 7;
        unsigned sb0 = (unsigned)__cvta_generic_to_shared(&skv[0][0]);
        unsigned sb1 = (unsigned)__cvta_generic_to_shared(&skv[1][0]);

        // prefetch tile 0
        {
            #pragma unroll
            for (int j = 0; j < 4; j++) {
                cpa16(sb0 + tid * 16 + j * 2048,        Kc + tid * 16 + j * 2048);
                cpa16(sb0 + 8192 + tid * 16 + j * 2048, Vc + tid * 16 + j * 2048);
            }
            cpa_commit();
        }

        for (int t = 0; t < nt; t++) {
            if (t + 1 < nt) {
                unsigned dst = ((t + 1) & 1) ? sb1 : sb0;
                size_t off = (size_t)(t + 1) * 8192;
                #pragma unroll
                for (int j = 0; j < 4; j++) {
                    cpa16(dst + tid * 16 + j * 2048,        Kc + off + tid * 16 + j * 2048);
                    cpa16(dst + 8192 + tid * 16 + j * 2048, Vc + off + tid * 16 + j * 2048);
                }
                cpa_commit();
                cpa_wait<1>();
            } else {
                cpa_wait<0>();
            }
            __syncthreads();
            const u64* buf = skv[t & 1];
            int nk = min(128, Lb - (t << 7));
            if (nk == 128) {
                #pragma unroll 2
                for (int k = 0; k < 128; k++)
                    qk2(buf, k, qa, qb, oa, ob, la, lb);
            } else {
                for (int k = 0; k < nk; k++)
                    qk2(buf, k, qa, qb, oa, ob, la, lb);
            }
            __syncthreads();
        }

        float ia = 1.f / la, ib = 1.f / lb;
        u64 ia2 = pack2(ia, ia), ib2 = pack2(ib, ib);
        u64* Oa = (u64*)(g_O + ((size_t)bh * SS + q0 + tid) * DH);
        u64* Ob = (u64*)(g_O + ((size_t)bh * SS + q0 + 128 + tid) * DH);
        #pragma unroll
        for (int j = 0; j < 8; j++) { Oa[j] = mul2(oa[j], ia2); Ob[j] = mul2(ob[j], ib2); }
    } else {
        // ----------------- tail mode: all 256 queries identical --------------
        u64 q[8], o[8];
        const u64* Qp = (const u64*)(g_Q + ((size_t)bh * SS + q0 + tid) * DH);
        #pragma unroll
        for (int j = 0; j < 8; j++) { q[j] = Qp[j]; o[j] = 0ull; }
        float l = 0.f;

        const ulonglong2* Kg = (const ulonglong2*)Kc;
        const ulonglong2* Vg = (const ulonglong2*)Vc;
        for (int k = tid; k < Lb; k += 128)
            qk1(Kg + (size_t)k * 4, Vg + (size_t)k * 4, q, o, l);

        float* sred = (float*)skv;               // 128 * 18 floats
        sred[tid * 18] = l;
        #pragma unroll
        for (int j = 0; j < 8; j++) {
            float2 p = unpk(o[j]);
            sred[tid * 18 + 1 + 2 * j] = p.x;
            sred[tid * 18 + 2 + 2 * j] = p.y;
        }
        __syncthreads();
        for (int off = 64; off > 0; off >>= 1) {
            if (tid < off) {
                float* p = sred + tid * 18;
                const float* r = sred + (tid + off) * 18;
                #pragma unroll
                for (int d = 0; d < 17; d++) p[d] += r[d];
            }
            __syncthreads();
        }
        l = sred[0];
        float inv = 1.f / l;
        u64 inv2 = pack2(inv, inv);
        u64 res[8];
        #pragma unroll
        for (int j = 0; j < 8; j++)
            res[j] = mul2(pack2(sred[1 + 2 * j], sred[2 + 2 * j]), inv2);
        u64* Oa = (u64*)(g_O + ((size_t)bh * SS + q0 + tid) * DH);
        u64* Ob = (u64*)(g_O + ((size_t)bh * SS + q0 + 128 + tid) * DH);
        #pragma unroll
        for (int j = 0; j < 8; j++) { Oa[j] = res[j]; Ob[j] = res[j]; }
    }
}

// ---------------------------------------------------------------------------
// K3: out = o_full @ wc^T + bc. Block = 256 threads, 128 tokens.
//     Coalesced smem-staged loads + stores; 2 threads/token with shfl combine.
// ---------------------------------------------------------------------------
#define TOK_STRIDE 36   // padded row stride (floats) in stok

__global__ void __launch_bounds__(256) out_kernel(float* __restrict__ out) {
    __shared__ __align__(16) float swc[VV * DD];
    __shared__ float sbc[VV];
    __shared__ __align__(16) float stok[128 * TOK_STRIDE];
    __shared__ __align__(16) float sout[128 * VV];

    int tid = threadIdx.x;
    for (int i = tid; i < VV * DD; i += 256) swc[i] = g_wc[i];
    if (tid < VV) sbc[tid] = g_bc[tid];

    int t0 = blockIdx.x * 128;
    int b  = t0 >> 10, s0 = t0 & 1023;

    // phase 1: coalesced load of both heads into stok[tok][0..31]
    const float4* h0 = (const float4*)(g_O + ((size_t)(b * 2 + 0) * SS + s0) * DH);
    const float4* h1 = (const float4*)(g_O + ((size_t)(b * 2 + 1) * SS + s0) * DH);
    #pragma unroll
    for (int r = 0; r < 2; r++) {
        int i = tid + r * 256;              // 512 float4 per head
        int tok = i >> 2, qq = i & 3;
        *(float4*)(stok + tok * TOK_STRIDE + qq * 4)      = h0[i];
        *(float4*)(stok + tok * TOK_STRIDE + 16 + qq * 4) = h1[i];
    }
    __syncthreads();

    // phase 2: 2 threads per token; each handles one 16-dim half, shfl combine
    int tok = tid >> 1, half = tid & 1;
    u64 o2[8];
    const u64* src = (const u64*)(stok + tok * TOK_STRIDE + half * 16);
    #pragma unroll
    for (int j = 0; j < 8; j++) o2[j] = src[j];

    #pragma unroll 4
    for (int v = 0; v < VV; v++) {
        const ulonglong2* wr = (const ulonglong2*)(swc + v * 32 + half * 16);
        ulonglong2 w0 = wr[0], w1 = wr[1], w2 = wr[2], w3 = wr[3];
        u64 a0 = mul2(o2[0], w0.x);
        u64 a1 = mul2(o2[1], w0.y);
        a0 = fma2(o2[2], w1.x, a0);  a1 = fma2(o2[3], w1.y, a1);
        a0 = fma2(o2[4], w2.x, a0);  a1 = fma2(o2[5], w2.y, a1);
        a0 = fma2(o2[6], w3.x, a0);  a1 = fma2(o2[7], w3.y, a1);
        float2 p = unpk(add2(a0, a1));
        float part = p.x + p.y;
        part += __shfl_xor_sync(0xffffffffu, part, 1);
        if (half == (v & 1))
            sout[tok * VV + v] = part + sbc[v];
    }
    __syncthreads();

    // phase 3: coalesced float4 store (128*28 = 3584 floats = 896 float4)
    float4* op = (float4*)(out + (size_t)t0 * VV);
    const float4* sp = (const float4*)sout;
    #pragma unroll
    for (int r = 0; r < 4; r++) {
        int i = tid + r * 256;
        if (i < 896) op[i] = sp[i];
    }
}

// ---------------------------------------------------------------------------
extern "C" void kernel_launch(void* const* d_in, const int* in_sizes, int n_in,
                              void* d_out, int out_size) {
    const int*   x    = (const int*)  d_in[0];
    const float* mask = (const float*)d_in[1];
    const float* emb  = (const float*)d_in[2];
    const float* pe   = (const float*)d_in[3];
    const float* wq   = (const float*)d_in[4];
    const float* bq   = (const float*)d_in[5];
    const float* wk   = (const float*)d_in[6];
    const float* bk   = (const float*)d_in[7];
    const float* wv   = (const float*)d_in[8];
    const float* bv   = (const float*)d_in[9];
    const float* wo   = (const float*)d_in[10];
    const float* bo   = (const float*)d_in[11];
    const float* wfc  = (const float*)d_in[12];
    const float* bfc  = (const float*)d_in[13];
    float* out = (float*)d_out;

    prep_kernel<<<BB + 1, 256>>>(mask, wo, bo, wfc, bfc);
    qkv_kernel<<<(BB * SS) / 256, 256>>>(x, emb, pe, wq, bq, wk, bk, wv, bv);
    attn_kernel<<<dim3(BB * HH, SS / 256), 128>>>();
    out_kernel<<<(BB * SS) / 128, 256>>>(out);
}

// round 11
// speedup vs baseline: 1.4643x; 1.4643x over previous
#include <cuda_runtime.h>

// Problem constants (fixed by the reference setup)
#define BB 64
#define SS 1024
#define DD 32
#define HH 2
#define DH 16
#define VV 28
#define LOG2E 1.44269504088896340736f
#define NKC_MAX 8   // max key chunks  (SS/128)
#define NQT_MAX 8   // max query tiles (SS/128)

#define NQ (BB * HH * SS * DH)

typedef unsigned long long u64;

// Scratch (no allocations allowed -> __device__ globals), 16B-aligned
__device__ __align__(16) float g_Q[NQ];
__device__ __align__(16) float g_K[NQ];
__device__ __align__(16) float g_V[NQ];
__device__ __align__(16) float g_O[NQ];
// split-K partials: [bh][kc][s][16] and [bh][kc][s]  (only live slots touched)
__device__ __align__(16) float g_Po[(size_t)BB * HH * NKC_MAX * SS * DH];
__device__ __align__(16) float g_Pl[(size_t)BB * HH * NKC_MAX * SS];
__device__ int   g_Lb[BB];
__device__ __align__(16) float g_wc[VV * DD];
__device__ float g_bc[VV];

// ---------------------------------------------------------------------------
// Packed f32x2 + misc PTX helpers
// ---------------------------------------------------------------------------
__device__ __forceinline__ u64 fma2(u64 a, u64 b, u64 c) {
    u64 d; asm("fma.rn.f32x2 %0,%1,%2,%3;" : "=l"(d) : "l"(a), "l"(b), "l"(c));
    return d;
}
__device__ __forceinline__ u64 mul2(u64 a, u64 b) {
    u64 d; asm("mul.rn.f32x2 %0,%1,%2;" : "=l"(d) : "l"(a), "l"(b));
    return d;
}
__device__ __forceinline__ u64 add2(u64 a, u64 b) {
    u64 d; asm("add.rn.f32x2 %0,%1,%2;" : "=l"(d) : "l"(a), "l"(b));
    return d;
}
__device__ __forceinline__ u64 pack2(float x, float y) {
    u64 r; asm("mov.b64 %0,{%1,%2};" : "=l"(r) : "f"(x), "f"(y));
    return r;
}
__device__ __forceinline__ float2 unpk(u64 v) {
    float2 r; asm("mov.b64 {%0,%1},%2;" : "=f"(r.x), "=f"(r.y) : "l"(v));
    return r;
}
__device__ __forceinline__ float ex2(float x) {
    float r; asm("ex2.approx.f32 %0,%1;" : "=f"(r) : "f"(x));
    return r;
}

// ---------------------------------------------------------------------------
// K0: per-batch prefix length Lb + combined output weights wc = w_fc @ wo
// ---------------------------------------------------------------------------
__global__ void prep_kernel(const float* __restrict__ mask,
                            const float* __restrict__ wo,
                            const float* __restrict__ bo,
                            const float* __restrict__ wfc,
                            const float* __restrict__ bfc) {
    int tid = threadIdx.x;
    int bb  = blockIdx.x;
    if (bb < BB) {
        __shared__ int smax[256];
        int mx = -1;
        const float* mp = mask + bb * SS;
        for (int s = tid; s < SS; s += 256)
            if (mp[s] > 0.f) mx = max(mx, s);
        smax[tid] = mx;
        __syncthreads();
        for (int off = 128; off > 0; off >>= 1) {
            if (tid < off) smax[tid] = max(smax[tid], smax[tid + off]);
            __syncthreads();
        }
        if (tid == 0) g_Lb[bb] = min(smax[0] + 4, SS - 1);
    } else {
        for (int e = tid; e < VV * DD; e += 256) {
            int v = e >> 5, d = e & 31;
            float acc = 0.f;
            #pragma unroll
            for (int t = 0; t < 32; t++)
                acc += wfc[v * 32 + t] * wo[t * 32 + d];
            g_wc[e] = acc;
        }
        if (tid < VV) {
            float acc = bfc[tid];
            #pragma unroll
            for (int t = 0; t < 32; t++)
                acc += wfc[tid * 32 + t] * bo[t];
            g_bc[tid] = acc;
        }
    }
}

// ---------------------------------------------------------------------------
// K1: QKV projections. Thread per token. Q pre-scaled by 0.25*log2(e) so the
//     attention kernel can use ex2 directly. Layout [B,H,S,DH].
// ---------------------------------------------------------------------------
__global__ void __launch_bounds__(256) qkv_kernel(
    const int* __restrict__ x,  const float* __restrict__ emb,
    const float* __restrict__ pe,
    const float* __restrict__ wq, const float* __restrict__ bq,
    const float* __restrict__ wk, const float* __restrict__ bk,
    const float* __restrict__ wv, const float* __restrict__ bv) {

    __shared__ __align__(16) float sw[3 * 1024 + 96];
    int tid = threadIdx.x;
    for (int i = tid; i < 1024; i += 256) {
        sw[i]        = wq[i];
        sw[1024 + i] = wk[i];
        sw[2048 + i] = wv[i];
    }
    if (tid < 32) {
        sw[3072 + tid] = bq[tid];
        sw[3104 + tid] = bk[tid];
        sw[3136 + tid] = bv[tid];
    }
    __syncthreads();

    int t = blockIdx.x * 256 + tid;
    int b = t >> 10, s = t & 1023;
    int Lb = g_Lb[b];
    const float QSCL = 0.25f * LOG2E;

    if (s >= Lb) {
        // masked token: h = 0 -> Q row is scaled bias; K/V rows never read
        #pragma unroll
        for (int j = 0; j < 32; j++) {
            int head = j >> 4, dd = j & 15;
            g_Q[((b * HH + head) * SS + s) * DH + dd] = sw[3072 + j] * QSCL;
        }
        return;
    }

    int xid = x[t];
    u64 h2[16];
    const float4* ep = (const float4*)(emb + xid * 32);
    const float4* pp = (const float4*)(pe + s * 32);
    #pragma unroll
    for (int j = 0; j < 8; j++) {
        float4 e4 = ep[j], p4 = pp[j];
        h2[2 * j]     = pack2(e4.x + p4.x, e4.y + p4.y);
        h2[2 * j + 1] = pack2(e4.z + p4.z, e4.w + p4.w);
    }

    #pragma unroll
    for (int mtx = 0; mtx < 3; mtx++) {
        const float* w    = sw + mtx * 1024;
        const float* bias = sw + 3072 + mtx * 32;
        float* outp = (mtx == 0) ? g_Q : ((mtx == 1) ? g_K : g_V);
        float scl = (mtx == 0) ? QSCL : 1.0f;
        #pragma unroll 4
        for (int j = 0; j < 32; j++) {
            const ulonglong2* wr = (const ulonglong2*)(w + j * 32);
            ulonglong2 w0 = wr[0], w1 = wr[1], w2 = wr[2], w3 = wr[3];
            ulonglong2 w4 = wr[4], w5 = wr[5], w6 = wr[6], w7 = wr[7];
            u64 a0 = mul2(h2[0], w0.x);
            u64 a1 = mul2(h2[1], w0.y);
            a0 = fma2(h2[2],  w1.x, a0);  a1 = fma2(h2[3],  w1.y, a1);
            a0 = fma2(h2[4],  w2.x, a0);  a1 = fma2(h2[5],  w2.y, a1);
            a0 = fma2(h2[6],  w3.x, a0);  a1 = fma2(h2[7],  w3.y, a1);
            a0 = fma2(h2[8],  w4.x, a0);  a1 = fma2(h2[9],  w4.y, a1);
            a0 = fma2(h2[10], w5.x, a0);  a1 = fma2(h2[11], w5.y, a1);
            a0 = fma2(h2[12], w6.x, a0);  a1 = fma2(h2[13], w6.y, a1);
            a0 = fma2(h2[14], w7.x, a0);  a1 = fma2(h2[15], w7.y, a1);
            float2 p = unpk(add2(a0, a1));
            float r = (p.x + p.y + bias[j]) * scl;
            int head = j >> 4, dd = j & 15;
            outp[((b * HH + head) * SS + s) * DH + dd] = r;
        }
    }
}

// ---------------------------------------------------------------------------
// K2: split-K attention. Grid (B*H, NQT_MAX, NKC_MAX), block = 128 threads =
//     one 128-query x 128-key tile; dead tiles early-exit. Uniform work per
//     live block -> near-perfect chip balance. No-max softmax makes partials
//     plain sums: each block writes (sum_e*v, sum_e) to its own slot.
// ---------------------------------------------------------------------------
__device__ __forceinline__ void qk1(const ulonglong2* __restrict__ kp,
                                    const ulonglong2* __restrict__ vp,
                                    const u64 q[8], u64 o[8], float& l) {
    ulonglong2 k0 = kp[0], k1 = kp[1], k2 = kp[2], k3 = kp[3];
    u64 a = mul2(q[0], k0.x);
    a = fma2(q[1], k0.y, a);
    a = fma2(q[2], k1.x, a);  a = fma2(q[3], k1.y, a);
    a = fma2(q[4], k2.x, a);  a = fma2(q[5], k2.y, a);
    a = fma2(q[6], k3.x, a);  a = fma2(q[7], k3.y, a);
    float2 p = unpk(a);
    float e = ex2(p.x + p.y);
    l += e;
    u64 e2 = pack2(e, e);
    ulonglong2 v0 = vp[0], v1 = vp[1], v2 = vp[2], v3 = vp[3];
    o[0] = fma2(e2, v0.x, o[0]);  o[1] = fma2(e2, v0.y, o[1]);
    o[2] = fma2(e2, v1.x, o[2]);  o[3] = fma2(e2, v1.y, o[3]);
    o[4] = fma2(e2, v2.x, o[4]);  o[5] = fma2(e2, v2.y, o[5]);
    o[6] = fma2(e2, v3.x, o[6]);  o[7] = fma2(e2, v3.y, o[7]);
}

__global__ void __launch_bounds__(128) attn_kernel() {
    __shared__ __align__(16) float sK[128 * DH];
    __shared__ __align__(16) float sV[128 * DH];

    int bh = blockIdx.x, qt = blockIdx.y, kc = blockIdx.z;
    int b  = bh >> 1;
    int tid = threadIdx.x;
    int Lb = g_Lb[b];
    int nqt = (Lb >> 7) + 1;           // query tiles: cover [0, Lb] inclusive
    int nkc = (Lb + 127) >> 7;         // key chunks over [0, Lb)
    if (qt >= nqt || kc >= nkc) return;

    int k0 = kc << 7;
    int nk = min(128, Lb - k0);

    // stage K/V chunk (coalesced float4)
    const float4* Kg = (const float4*)(g_K + ((size_t)bh * SS + k0) * DH);
    const float4* Vg = (const float4*)(g_V + ((size_t)bh * SS + k0) * DH);
    int nf = nk * 4;
    for (int i = tid; i < nf; i += 128) {
        ((float4*)sK)[i] = Kg[i];
        ((float4*)sV)[i] = Vg[i];
    }
    __syncthreads();

    u64 q[8], o[8];
    const u64* Qp = (const u64*)(g_Q + ((size_t)bh * SS + (qt << 7) + tid) * DH);
    #pragma unroll
    for (int j = 0; j < 8; j++) { q[j] = Qp[j]; o[j] = 0ull; }
    float l = 0.f;

    const u64* sKu = (const u64*)sK;
    const u64* sVu = (const u64*)sV;
    if (nk == 128) {
        #pragma unroll 2
        for (int k = 0; k < 128; k++)
            qk1((const ulonglong2*)(sKu + k * 8), (const ulonglong2*)(sVu + k * 8), q, o, l);
    } else {
        for (int k = 0; k < nk; k++)
            qk1((const ulonglong2*)(sKu + k * 8), (const ulonglong2*)(sVu + k * 8), q, o, l);
    }

    // write this chunk's partial (deterministic slot, no atomics)
    size_t base = ((size_t)bh * NKC_MAX + kc) * SS + (qt << 7) + tid;
    float4* Po = (float4*)(g_Po + base * DH);
    #pragma unroll
    for (int j = 0; j < 4; j++) {
        float2 pa = unpk(o[2 * j]), pb = unpk(o[2 * j + 1]);
        Po[j] = make_float4(pa.x, pa.y, pb.x, pb.y);
    }
    g_Pl[base] = l;
}

// ---------------------------------------------------------------------------
// K2b: combine split-K partials and normalize -> g_O. Grid (B*H, NQT_MAX).
// ---------------------------------------------------------------------------
__global__ void __launch_bounds__(128) reduce_kernel() {
    int bh = blockIdx.x, qt = blockIdx.y, tid = threadIdx.x;
    int b  = bh >> 1;
    int Lb = g_Lb[b];
    int nqt = (Lb >> 7) + 1;
    int nkc = (Lb + 127) >> 7;
    if (qt >= nqt) return;

    int s = (qt << 7) + tid;
    float l = 0.f;
    float4 o0 = make_float4(0, 0, 0, 0), o1 = o0, o2 = o0, o3 = o0;
    for (int kc = 0; kc < nkc; kc++) {
        size_t base = ((size_t)bh * NKC_MAX + kc) * SS + s;
        l += g_Pl[base];
        const float4* Po = (const float4*)(g_Po + base * DH);
        float4 t0 = Po[0], t1 = Po[1], t2 = Po[2], t3 = Po[3];
        o0.x += t0.x; o0.y += t0.y; o0.z += t0.z; o0.w += t0.w;
        o1.x += t1.x; o1.y += t1.y; o1.z += t1.z; o1.w += t1.w;
        o2.x += t2.x; o2.y += t2.y; o2.z += t2.z; o2.w += t2.w;
        o3.x += t3.x; o3.y += t3.y; o3.z += t3.z; o3.w += t3.w;
    }
    float inv = 1.f / l;
    float4* O = (float4*)(g_O + ((size_t)bh * SS + s) * DH);
    O[0] = make_float4(o0.x * inv, o0.y * inv, o0.z * inv, o0.w * inv);
    O[1] = make_float4(o1.x * inv, o1.y * inv, o1.z * inv, o1.w * inv);
    O[2] = make_float4(o2.x * inv, o2.y * inv, o2.z * inv, o2.w * inv);
    O[3] = make_float4(o3.x * inv, o3.y * inv, o3.z * inv, o3.w * inv);
}

// ---------------------------------------------------------------------------
// K3: out = o_full @ wc^T + bc. Block = 256 threads, 128 tokens.
//     Tail tokens (s >= qlim) remap to the representative row at index Lb
//     (all tail queries are identical).
// ---------------------------------------------------------------------------
#define TOK_STRIDE 36   // padded row stride (floats) in stok

__global__ void __launch_bounds__(256) out_kernel(float* __restrict__ out) {
    __shared__ __align__(16) float swc[VV * DD];
    __shared__ float sbc[VV];
    __shared__ __align__(16) float stok[128 * TOK_STRIDE];
    __shared__ __align__(16) float sout[128 * VV];

    int tid = threadIdx.x;
    for (int i = tid; i < VV * DD; i += 256) swc[i] = g_wc[i];
    if (tid < VV) sbc[tid] = g_bc[tid];

    int t0 = blockIdx.x * 128;
    int b  = t0 >> 10, s0 = t0 & 1023;
    int Lb = g_Lb[b];
    int qlim = ((Lb >> 7) + 1) << 7;   // rows [0, qlim) were computed

    // phase 1: load both heads into stok[tok][0..31] (tail rows remapped)
    const float4* h0 = (const float4*)(g_O + (size_t)(b * 2 + 0) * SS * DH);
    const float4* h1 = (const float4*)(g_O + (size_t)(b * 2 + 1) * SS * DH);
    #pragma unroll
    for (int r = 0; r < 2; r++) {
        int i = tid + r * 256;              // 512 float4 per head
        int tok = i >> 2, qq = i & 3;
        int s = s0 + tok;
        int se = (s < qlim) ? s : Lb;
        *(float4*)(stok + tok * TOK_STRIDE + qq * 4)      = h0[se * 4 + qq];
        *(float4*)(stok + tok * TOK_STRIDE + 16 + qq * 4) = h1[se * 4 + qq];
    }
    __syncthreads();

    // phase 2: 2 threads per token; each handles one 16-dim half, shfl combine
    int tok = tid >> 1, half = tid & 1;
    u64 o2[8];
    const u64* src = (const u64*)(stok + tok * TOK_STRIDE + half * 16);
    #pragma unroll
    for (int j = 0; j < 8; j++) o2[j] = src[j];

    #pragma unroll 4
    for (int v = 0; v < VV; v++) {
        const ulonglong2* wr = (const ulonglong2*)(swc + v * 32 + half * 16);
        ulonglong2 w0 = wr[0], w1 = wr[1], w2 = wr[2], w3 = wr[3];
        u64 a0 = mul2(o2[0], w0.x);
        u64 a1 = mul2(o2[1], w0.y);
        a0 = fma2(o2[2], w1.x, a0);  a1 = fma2(o2[3], w1.y, a1);
        a0 = fma2(o2[4], w2.x, a0);  a1 = fma2(o2[5], w2.y, a1);
        a0 = fma2(o2[6], w3.x, a0);  a1 = fma2(o2[7], w3.y, a1);
        float2 p = unpk(add2(a0, a1));
        float part = p.x + p.y;
        part += __shfl_xor_sync(0xffffffffu, part, 1);
        if (half == (v & 1))
            sout[tok * VV + v] = part + sbc[v];
    }
    __syncthreads();

    // phase 3: coalesced float4 store (128*28 = 3584 floats = 896 float4)
    float4* op = (float4*)(out + (size_t)t0 * VV);
    const float4* sp = (const float4*)sout;
    #pragma unroll
    for (int r = 0; r < 4; r++) {
        int i = tid + r * 256;
        if (i < 896) op[i] = sp[i];
    }
}

// ---------------------------------------------------------------------------
extern "C" void kernel_launch(void* const* d_in, const int* in_sizes, int n_in,
                              void* d_out, int out_size) {
    const int*   x    = (const int*)  d_in[0];
    const float* mask = (const float*)d_in[1];
    const float* emb  = (const float*)d_in[2];
    const float* pe   = (const float*)d_in[3];
    const float* wq   = (const float*)d_in[4];
    const float* bq   = (const float*)d_in[5];
    const float* wk   = (const float*)d_in[6];
    const float* bk   = (const float*)d_in[7];
    const float* wv   = (const float*)d_in[8];
    const float* bv   = (const float*)d_in[9];
    const float* wo   = (const float*)d_in[10];
    const float* bo   = (const float*)d_in[11];
    const float* wfc  = (const float*)d_in[12];
    const float* bfc  = (const float*)d_in[13];
    float* out = (float*)d_out;

    prep_kernel<<<BB + 1, 256>>>(mask, wo, bo, wfc, bfc);
    qkv_kernel<<<(BB * SS) / 256, 256>>>(x, emb, pe, wq, bq, wk, bk, wv, bv);
    attn_kernel<<<dim3(BB * HH, NQT_MAX, NKC_MAX), 128>>>();
    reduce_kernel<<<dim3(BB * HH, NQT_MAX), 128>>>();
    out_kernel<<<(BB * SS) / 128, 256>>>(out);
}

// round 12
// speedup vs baseline: 1.4687x; 1.0030x over previous
#include <cuda_runtime.h>

// Problem constants (fixed by the reference setup)
#define BB 64
#define SS 1024
#define DD 32
#define HH 2
#define DH 16
#define VV 28
#define LOG2E 1.44269504088896340736f
#define KC 256      // keys per split-K chunk
#define NKC_MAX 4   // max key chunks  (SS/KC)
#define NQT_MAX 8   // max query tiles (SS/128)

#define NQ (BB * HH * SS * DH)

typedef unsigned long long u64;

// Scratch (no allocations allowed -> __device__ globals), 16B-aligned
__device__ __align__(16) float g_Q[NQ];
__device__ __align__(16) float g_K[NQ];
__device__ __align__(16) float g_V[NQ];
__device__ __align__(16) float g_O[NQ];
// split-K partials: [bh][kc][s][16] and [bh][kc][s]  (only live slots touched)
__device__ __align__(16) float g_Po[(size_t)BB * HH * NKC_MAX * SS * DH];
__device__ __align__(16) float g_Pl[(size_t)BB * HH * NKC_MAX * SS];
__device__ int   g_Lb[BB];
__device__ __align__(16) float g_wc[VV * DD];
__device__ float g_bc[VV];

// ---------------------------------------------------------------------------
// Packed f32x2 + misc PTX helpers
// ---------------------------------------------------------------------------
__device__ __forceinline__ u64 fma2(u64 a, u64 b, u64 c) {
    u64 d; asm("fma.rn.f32x2 %0,%1,%2,%3;" : "=l"(d) : "l"(a), "l"(b), "l"(c));
    return d;
}
__device__ __forceinline__ u64 mul2(u64 a, u64 b) {
    u64 d; asm("mul.rn.f32x2 %0,%1,%2;" : "=l"(d) : "l"(a), "l"(b));
    return d;
}
__device__ __forceinline__ u64 add2(u64 a, u64 b) {
    u64 d; asm("add.rn.f32x2 %0,%1,%2;" : "=l"(d) : "l"(a), "l"(b));
    return d;
}
__device__ __forceinline__ u64 pack2(float x, float y) {
    u64 r; asm("mov.b64 %0,{%1,%2};" : "=l"(r) : "f"(x), "f"(y));
    return r;
}
__device__ __forceinline__ float2 unpk(u64 v) {
    float2 r; asm("mov.b64 {%0,%1},%2;" : "=f"(r.x), "=f"(r.y) : "l"(v));
    return r;
}
__device__ __forceinline__ float ex2(float x) {
    float r; asm("ex2.approx.f32 %0,%1;" : "=f"(r) : "f"(x));
    return r;
}

// ---------------------------------------------------------------------------
// K0: per-batch prefix length Lb + combined output weights wc = w_fc @ wo
// ---------------------------------------------------------------------------
__global__ void prep_kernel(const float* __restrict__ mask,
                            const float* __restrict__ wo,
                            const float* __restrict__ bo,
                            const float* __restrict__ wfc,
                            const float* __restrict__ bfc) {
    int tid = threadIdx.x;
    int bb  = blockIdx.x;
    if (bb < BB) {
        __shared__ int smax[256];
        int mx = -1;
        const float* mp = mask + bb * SS;
        for (int s = tid; s < SS; s += 256)
            if (mp[s] > 0.f) mx = max(mx, s);
        smax[tid] = mx;
        __syncthreads();
        for (int off = 128; off > 0; off >>= 1) {
            if (tid < off) smax[tid] = max(smax[tid], smax[tid + off]);
            __syncthreads();
        }
        if (tid == 0) g_Lb[bb] = min(smax[0] + 4, SS - 1);
    } else {
        for (int e = tid; e < VV * DD; e += 256) {
            int v = e >> 5, d = e & 31;
            float acc = 0.f;
            #pragma unroll
            for (int t = 0; t < 32; t++)
                acc += wfc[v * 32 + t] * wo[t * 32 + d];
            g_wc[e] = acc;
        }
        if (tid < VV) {
            float acc = bfc[tid];
            #pragma unroll
            for (int t = 0; t < 32; t++)
                acc += wfc[tid * 32 + t] * bo[t];
            g_bc[tid] = acc;
        }
    }
}

// ---------------------------------------------------------------------------
// K1: QKV projections. Thread per token. Q pre-scaled by 0.25*log2(e) so the
//     attention kernel can use ex2 directly. Layout [B,H,S,DH].
// ---------------------------------------------------------------------------
__global__ void __launch_bounds__(256) qkv_kernel(
    const int* __restrict__ x,  const float* __restrict__ emb,
    const float* __restrict__ pe,
    const float* __restrict__ wq, const float* __restrict__ bq,
    const float* __restrict__ wk, const float* __restrict__ bk,
    const float* __restrict__ wv, const float* __restrict__ bv) {

    __shared__ __align__(16) float sw[3 * 1024 + 96];
    int tid = threadIdx.x;
    for (int i = tid; i < 1024; i += 256) {
        sw[i]        = wq[i];
        sw[1024 + i] = wk[i];
        sw[2048 + i] = wv[i];
    }
    if (tid < 32) {
        sw[3072 + tid] = bq[tid];
        sw[3104 + tid] = bk[tid];
        sw[3136 + tid] = bv[tid];
    }
    __syncthreads();

    int t = blockIdx.x * 256 + tid;
    int b = t >> 10, s = t & 1023;
    int Lb = g_Lb[b];
    const float QSCL = 0.25f * LOG2E;

    if (s >= Lb) {
        // masked token: h = 0 -> Q row is scaled bias; K/V rows never read
        #pragma unroll
        for (int j = 0; j < 32; j++) {
            int head = j >> 4, dd = j & 15;
            g_Q[((b * HH + head) * SS + s) * DH + dd] = sw[3072 + j] * QSCL;
        }
        return;
    }

    int xid = x[t];
    u64 h2[16];
    const float4* ep = (const float4*)(emb + xid * 32);
    const float4* pp = (const float4*)(pe + s * 32);
    #pragma unroll
    for (int j = 0; j < 8; j++) {
        float4 e4 = ep[j], p4 = pp[j];
        h2[2 * j]     = pack2(e4.x + p4.x, e4.y + p4.y);
        h2[2 * j + 1] = pack2(e4.z + p4.z, e4.w + p4.w);
    }

    #pragma unroll
    for (int mtx = 0; mtx < 3; mtx++) {
        const float* w    = sw + mtx * 1024;
        const float* bias = sw + 3072 + mtx * 32;
        float* outp = (mtx == 0) ? g_Q : ((mtx == 1) ? g_K : g_V);
        float scl = (mtx == 0) ? QSCL : 1.0f;
        #pragma unroll 4
        for (int j = 0; j < 32; j++) {
            const ulonglong2* wr = (const ulonglong2*)(w + j * 32);
            ulonglong2 w0 = wr[0], w1 = wr[1], w2 = wr[2], w3 = wr[3];
            ulonglong2 w4 = wr[4], w5 = wr[5], w6 = wr[6], w7 = wr[7];
            u64 a0 = mul2(h2[0], w0.x);
            u64 a1 = mul2(h2[1], w0.y);
            a0 = fma2(h2[2],  w1.x, a0);  a1 = fma2(h2[3],  w1.y, a1);
            a0 = fma2(h2[4],  w2.x, a0);  a1 = fma2(h2[5],  w2.y, a1);
            a0 = fma2(h2[6],  w3.x, a0);  a1 = fma2(h2[7],  w3.y, a1);
            a0 = fma2(h2[8],  w4.x, a0);  a1 = fma2(h2[9],  w4.y, a1);
            a0 = fma2(h2[10], w5.x, a0);  a1 = fma2(h2[11], w5.y, a1);
            a0 = fma2(h2[12], w6.x, a0);  a1 = fma2(h2[13], w6.y, a1);
            a0 = fma2(h2[14], w7.x, a0);  a1 = fma2(h2[15], w7.y, a1);
            float2 p = unpk(add2(a0, a1));
            float r = (p.x + p.y + bias[j]) * scl;
            int head = j >> 4, dd = j & 15;
            outp[((b * HH + head) * SS + s) * DH + dd] = r;
        }
    }
}

// ---------------------------------------------------------------------------
// K2: split-K attention. Grid (B*H, NQT_MAX, NKC_MAX), block = 128 threads =
//     one 128-query x 256-key tile; dead tiles early-exit. Uniform work per
//     live block -> near-perfect chip balance. No-max softmax makes partials
//     plain sums: each block writes (sum_e*v, sum_e) to its own slot.
// ---------------------------------------------------------------------------
__device__ __forceinline__ void qk1(const ulonglong2* __restrict__ kp,
                                    const ulonglong2* __restrict__ vp,
                                    const u64 q[8], u64 o[8], float& l) {
    ulonglong2 k0 = kp[0], k1 = kp[1], k2 = kp[2], k3 = kp[3];
    u64 a0 = mul2(q[0], k0.x);
    u64 a1 = mul2(q[1], k0.y);
    a0 = fma2(q[2], k1.x, a0);  a1 = fma2(q[3], k1.y, a1);
    a0 = fma2(q[4], k2.x, a0);  a1 = fma2(q[5], k2.y, a1);
    a0 = fma2(q[6], k3.x, a0);  a1 = fma2(q[7], k3.y, a1);
    float2 p = unpk(add2(a0, a1));
    float e = ex2(p.x + p.y);
    l += e;
    u64 e2 = pack2(e, e);
    ulonglong2 v0 = vp[0], v1 = vp[1], v2 = vp[2], v3 = vp[3];
    o[0] = fma2(e2, v0.x, o[0]);  o[1] = fma2(e2, v0.y, o[1]);
    o[2] = fma2(e2, v1.x, o[2]);  o[3] = fma2(e2, v1.y, o[3]);
    o[4] = fma2(e2, v2.x, o[4]);  o[5] = fma2(e2, v2.y, o[5]);
    o[6] = fma2(e2, v3.x, o[6]);  o[7] = fma2(e2, v3.y, o[7]);
}

__global__ void __launch_bounds__(128) attn_kernel() {
    __shared__ __align__(16) float sK[KC * DH];   // 16 KB
    __shared__ __align__(16) float sV[KC * DH];   // 16 KB

    int bh = blockIdx.x, qt = blockIdx.y, kc = blockIdx.z;
    int b  = bh >> 1;
    int tid = threadIdx.x;
    int Lb = g_Lb[b];
    int nqt = (Lb >> 7) + 1;             // query tiles: cover [0, Lb] inclusive
    int nkc = (Lb + KC - 1) >> 8;        // key chunks over [0, Lb)
    if (qt >= nqt || kc >= nkc) return;

    int k0 = kc << 8;
    int nk = min(KC, Lb - k0);

    // stage K/V chunk (coalesced float4)
    const float4* Kg = (const float4*)(g_K + ((size_t)bh * SS + k0) * DH);
    const float4* Vg = (const float4*)(g_V + ((size_t)bh * SS + k0) * DH);
    int nf = nk * 4;
    for (int i = tid; i < nf; i += 128) {
        ((float4*)sK)[i] = Kg[i];
        ((float4*)sV)[i] = Vg[i];
    }
    __syncthreads();

    u64 q[8], o[8];
    const u64* Qp = (const u64*)(g_Q + ((size_t)bh * SS + (qt << 7) + tid) * DH);
    #pragma unroll
    for (int j = 0; j < 8; j++) { q[j] = Qp[j]; o[j] = 0ull; }
    float l = 0.f;

    const u64* sKu = (const u64*)sK;
    const u64* sVu = (const u64*)sV;
    if (nk == KC) {
        #pragma unroll 2
        for (int k = 0; k < KC; k++)
            qk1((const ulonglong2*)(sKu + k * 8), (const ulonglong2*)(sVu + k * 8), q, o, l);
    } else {
        for (int k = 0; k < nk; k++)
            qk1((const ulonglong2*)(sKu + k * 8), (const ulonglong2*)(sVu + k * 8), q, o, l);
    }

    // write this chunk's partial (deterministic slot, no atomics)
    size_t base = ((size_t)bh * NKC_MAX + kc) * SS + (qt << 7) + tid;
    float4* Po = (float4*)(g_Po + base * DH);
    #pragma unroll
    for (int j = 0; j < 4; j++) {
        float2 pa = unpk(o[2 * j]), pb = unpk(o[2 * j + 1]);
        Po[j] = make_float4(pa.x, pa.y, pb.x, pb.y);
    }
    g_Pl[base] = l;
}

// ---------------------------------------------------------------------------
// K2b: combine split-K partials and normalize -> g_O. Grid (B*H, NQT_MAX).
// ---------------------------------------------------------------------------
__global__ void __launch_bounds__(128) reduce_kernel() {
    int bh = blockIdx.x, qt = blockIdx.y, tid = threadIdx.x;
    int b  = bh >> 1;
    int Lb = g_Lb[b];
    int nqt = (Lb >> 7) + 1;
    int nkc = (Lb + KC - 1) >> 8;
    if (qt >= nqt) return;

    int s = (qt << 7) + tid;
    float l = 0.f;
    float4 o0 = make_float4(0, 0, 0, 0), o1 = o0, o2 = o0, o3 = o0;
    #pragma unroll 4
    for (int kc = 0; kc < nkc; kc++) {
        size_t base = ((size_t)bh * NKC_MAX + kc) * SS + s;
        l += g_Pl[base];
        const float4* Po = (const float4*)(g_Po + base * DH);
        float4 t0 = Po[0], t1 = Po[1], t2 = Po[2], t3 = Po[3];
        o0.x += t0.x; o0.y += t0.y; o0.z += t0.z; o0.w += t0.w;
        o1.x += t1.x; o1.y += t1.y; o1.z += t1.z; o1.w += t1.w;
        o2.x += t2.x; o2.y += t2.y; o2.z += t2.z; o2.w += t2.w;
        o3.x += t3.x; o3.y += t3.y; o3.z += t3.z; o3.w += t3.w;
    }
    float inv = 1.f / l;
    float4* O = (float4*)(g_O + ((size_t)bh * SS + s) * DH);
    O[0] = make_float4(o0.x * inv, o0.y * inv, o0.z * inv, o0.w * inv);
    O[1] = make_float4(o1.x * inv, o1.y * inv, o1.z * inv, o1.w * inv);
    O[2] = make_float4(o2.x * inv, o2.y * inv, o2.z * inv, o2.w * inv);
    O[3] = make_float4(o3.x * inv, o3.y * inv, o3.z * inv, o3.w * inv);
}

// ---------------------------------------------------------------------------
// K3: out = o_full @ wc^T + bc. Block = 256 threads, 128 tokens.
//     2 threads/token split BY OUTPUT (14 each) -> no shfl, no predication.
//     Tail tokens (s >= qlim) remap to the representative row at index Lb.
// ---------------------------------------------------------------------------
#define TOK_STRIDE 36   // padded row stride (floats) in stok

__global__ void __launch_bounds__(256) out_kernel(float* __restrict__ out) {
    __shared__ __align__(16) float swc[VV * DD];
    __shared__ float sbc[VV];
    __shared__ __align__(16) float stok[128 * TOK_STRIDE];
    __shared__ __align__(16) float sout[128 * VV];

    int tid = threadIdx.x;
    for (int i = tid; i < VV * DD; i += 256) swc[i] = g_wc[i];
    if (tid < VV) sbc[tid] = g_bc[tid];

    int t0 = blockIdx.x * 128;
    int b  = t0 >> 10, s0 = t0 & 1023;
    int Lb = g_Lb[b];
    int qlim = ((Lb >> 7) + 1) << 7;   // rows [0, qlim) were computed

    // phase 1: load both heads into stok[tok][0..31] (tail rows remapped)
    const float4* h0 = (const float4*)(g_O + (size_t)(b * 2 + 0) * SS * DH);
    const float4* h1 = (const float4*)(g_O + (size_t)(b * 2 + 1) * SS * DH);
    #pragma unroll
    for (int r = 0; r < 2; r++) {
        int i = tid + r * 256;              // 512 float4 per head
        int tok = i >> 2, qq = i & 3;
        int s = s0 + tok;
        int se = (s < qlim) ? s : Lb;
        *(float4*)(stok + tok * TOK_STRIDE + qq * 4)      = h0[se * 4 + qq];
        *(float4*)(stok + tok * TOK_STRIDE + 16 + qq * 4) = h1[se * 4 + qq];
    }
    __syncthreads();

    // phase 2: 2 threads per token; each computes 14 full-width outputs
    int tok = tid >> 1, half = tid & 1;
    u64 o2[16];
    const u64* src = (const u64*)(stok + tok * TOK_STRIDE);
    #pragma unroll
    for (int j = 0; j < 16; j++) o2[j] = src[j];

    #pragma unroll 2
    for (int vi = 0; vi < 14; vi++) {
        int v = half * 14 + vi;
        const ulonglong2* wr = (const ulonglong2*)(swc + v * 32);
        ulonglong2 w0 = wr[0], w1 = wr[1], w2 = wr[2], w3 = wr[3];
        ulonglong2 w4 = wr[4], w5 = wr[5], w6 = wr[6], w7 = wr[7];
        u64 a0 = mul2(o2[0], w0.x);
        u64 a1 = mul2(o2[1], w0.y);
        a0 = fma2(o2[2],  w1.x, a0);  a1 = fma2(o2[3],  w1.y, a1);
        a0 = fma2(o2[4],  w2.x, a0);  a1 = fma2(o2[5],  w2.y, a1);
        a0 = fma2(o2[6],  w3.x, a0);  a1 = fma2(o2[7],  w3.y, a1);
        a0 = fma2(o2[8],  w4.x, a0);  a1 = fma2(o2[9],  w4.y, a1);
        a0 = fma2(o2[10], w5.x, a0);  a1 = fma2(o2[11], w5.y, a1);
        a0 = fma2(o2[12], w6.x, a0);  a1 = fma2(o2[13], w6.y, a1);
        a0 = fma2(o2[14], w7.x, a0);  a1 = fma2(o2[15], w7.y, a1);
        float2 p = unpk(add2(a0, a1));
        sout[tok * VV + v] = p.x + p.y + sbc[v];
    }
    __syncthreads();

    // phase 3: coalesced float4 store (128*28 = 3584 floats = 896 float4)
    float4* op = (float4*)(out + (size_t)t0 * VV);
    const float4* sp = (const float4*)sout;
    #pragma unroll
    for (int r = 0; r < 4; r++) {
        int i = tid + r * 256;
        if (i < 896) op[i] = sp[i];
    }
}

// ---------------------------------------------------------------------------
extern "C" void kernel_launch(void* const* d_in, const int* in_sizes, int n_in,
                              void* d_out, int out_size) {
    const int*   x    = (const int*)  d_in[0];
    const float* mask = (const float*)d_in[1];
    const float* emb  = (const float*)d_in[2];
    const float* pe   = (const float*)d_in[3];
    const float* wq   = (const float*)d_in[4];
    const float* bq   = (const float*)d_in[5];
    const float* wk   = (const float*)d_in[6];
    const float* bk   = (const float*)d_in[7];
    const float* wv   = (const float*)d_in[8];
    const float* bv   = (const float*)d_in[9];
    const float* wo   = (const float*)d_in[10];
    const float* bo   = (const float*)d_in[11];
    const float* wfc  = (const float*)d_in[12];
    const float* bfc  = (const float*)d_in[13];
    float* out = (float*)d_out;

    prep_kernel<<<BB + 1, 256>>>(mask, wo, bo, wfc, bfc);
    qkv_kernel<<<(BB * SS) / 256, 256>>>(x, emb, pe, wq, bq, wk, bk, wv, bv);
    attn_kernel<<<dim3(BB * HH, NQT_MAX, NKC_MAX), 128>>>();
    reduce_kernel<<<dim3(BB * HH, NQT_MAX), 128>>>();
    out_kernel<<<(BB * SS) / 128, 256>>>(out);
}

// round 14
// speedup vs baseline: 1.6309x; 1.1105x over previous
#include <cuda_runtime.h>

// Problem constants (fixed by the reference setup)
#define BB 64
#define SS 1024
#define DD 32
#define HH 2
#define DH 16
#define VV 28
#define LOG2E 1.44269504088896340736f
#define KC 256      // keys per split-K chunk
#define NKC_MAX 4   // max key chunks  (SS/KC)
#define NQT_MAX 8   // max query tiles (SS/128)
#define TS 36       // token stage stride in floats (multiple of 4 -> aligned)

#define NQ (BB * HH * SS * DH)

typedef unsigned long long u64;

// Scratch (no allocations allowed -> __device__ globals), 16B-aligned
// Q in tile-SoA layout: [bh][qt][j:4][128] float4 planes (thread-contiguous)
__device__ __align__(16) float g_Qt[NQ];
__device__ __align__(16) float g_K[NQ];     // row-major [bh][s][16]
__device__ __align__(16) float g_V[NQ];
// split-K partials, tile-SoA: [bh][kc][qt][j:4][128] float4 + [bh][kc][qt][128]
__device__ __align__(16) float g_Po[(size_t)BB * HH * NKC_MAX * NQT_MAX * 128 * DH];
__device__ __align__(16) float g_Pl[(size_t)BB * HH * NKC_MAX * NQT_MAX * 128];
__device__ int   g_Lb[BB];
__device__ __align__(16) float g_wc[VV * DD];
__device__ float g_bc[VV];

// ---------------------------------------------------------------------------
// Packed f32x2 + misc PTX helpers
// ---------------------------------------------------------------------------
__device__ __forceinline__ u64 fma2(u64 a, u64 b, u64 c) {
    u64 d; asm("fma.rn.f32x2 %0,%1,%2,%3;" : "=l"(d) : "l"(a), "l"(b), "l"(c));
    return d;
}
__device__ __forceinline__ u64 mul2(u64 a, u64 b) {
    u64 d; asm("mul.rn.f32x2 %0,%1,%2;" : "=l"(d) : "l"(a), "l"(b));
    return d;
}
__device__ __forceinline__ u64 add2(u64 a, u64 b) {
    u64 d; asm("add.rn.f32x2 %0,%1,%2;" : "=l"(d) : "l"(a), "l"(b));
    return d;
}
__device__ __forceinline__ u64 pack2(float x, float y) {
    u64 r; asm("mov.b64 %0,{%1,%2};" : "=l"(r) : "f"(x), "f"(y));
    return r;
}
__device__ __forceinline__ float2 unpk(u64 v) {
    float2 r; asm("mov.b64 {%0,%1},%2;" : "=f"(r.x), "=f"(r.y) : "l"(v));
    return r;
}
__device__ __forceinline__ float ex2(float x) {
    float r; asm("ex2.approx.f32 %0,%1;" : "=f"(r) : "f"(x));
    return r;
}

// ---------------------------------------------------------------------------
// K0: per-batch prefix length Lb + combined output weights wc = w_fc @ wo
// ---------------------------------------------------------------------------
__global__ void prep_kernel(const float* __restrict__ mask,
                            const float* __restrict__ wo,
                            const float* __restrict__ bo,
                            const float* __restrict__ wfc,
                            const float* __restrict__ bfc) {
    int tid = threadIdx.x;
    int bb  = blockIdx.x;
    if (bb < BB) {
        __shared__ int smax[256];
        int mx = -1;
        const float* mp = mask + bb * SS;
        for (int s = tid; s < SS; s += 256)
            if (mp[s] > 0.f) mx = max(mx, s);
        smax[tid] = mx;
        __syncthreads();
        for (int off = 128; off > 0; off >>= 1) {
            if (tid < off) smax[tid] = max(smax[tid], smax[tid + off]);
            __syncthreads();
        }
        if (tid == 0) g_Lb[bb] = min(smax[0] + 4, SS - 1);
    } else {
        for (int e = tid; e < VV * DD; e += 256) {
            int v = e >> 5, d = e & 31;
            float acc = 0.f;
            #pragma unroll
            for (int t = 0; t < 32; t++)
                acc += wfc[v * 32 + t] * wo[t * 32 + d];
            g_wc[e] = acc;
        }
        if (tid < VV) {
            float acc = bfc[tid];
            #pragma unroll
            for (int t = 0; t < 32; t++)
                acc += wfc[tid * 32 + t] * bo[t];
            g_bc[tid] = acc;
        }
    }
}

// ---------------------------------------------------------------------------
// K1: QKV projections, 256 tokens/block (one batch b). One weight matrix
//     staged in smem at a time (keeps static smem < 48 KB with the padded
//     token stage). Outputs staged at stride TS=36 (float4-aligned), then
//     written COALESCED: Q tile-SoA, K/V row-major. Q pre-scaled 0.25*log2e.
// ---------------------------------------------------------------------------
__global__ void __launch_bounds__(256) qkv_kernel(
    const int* __restrict__ x,  const float* __restrict__ emb,
    const float* __restrict__ pe,
    const float* __restrict__ wq, const float* __restrict__ bq,
    const float* __restrict__ wk, const float* __restrict__ bk,
    const float* __restrict__ wv, const float* __restrict__ bv) {

    __shared__ __align__(16) float sw[1024 + 32];
    __shared__ __align__(16) float so[256 * TS];     // 36 KB
    int tid = threadIdx.x;

    int t0 = blockIdx.x * 256;
    int b  = t0 >> 10, s0 = t0 & 1023;
    int s  = s0 + tid;
    int Lb = g_Lb[b];
    const float QSCL = 0.25f * LOG2E;
    bool live = (s < Lb);

    u64 h2[16];
    if (live) {
        int xid = x[t0 + tid];
        const float4* ep = (const float4*)(emb + xid * 32);
        const float4* pp = (const float4*)(pe + s * 32);
        #pragma unroll
        for (int j = 0; j < 8; j++) {
            float4 e4 = ep[j], p4 = pp[j];
            h2[2 * j]     = pack2(e4.x + p4.x, e4.y + p4.y);
            h2[2 * j + 1] = pack2(e4.z + p4.z, e4.w + p4.w);
        }
    }

    #pragma unroll
    for (int mtx = 0; mtx < 3; mtx++) {
        const float* wg = (mtx == 0) ? wq : ((mtx == 1) ? wk : wv);
        const float* bg = (mtx == 0) ? bq : ((mtx == 1) ? bk : bv);
        float scl = (mtx == 0) ? QSCL : 1.0f;

        for (int i = tid; i < 1024; i += 256) sw[i] = wg[i];
        if (tid < 32) sw[1024 + tid] = bg[tid];
        __syncthreads();

        if (live) {
            #pragma unroll 4
            for (int j = 0; j < 32; j++) {
                const ulonglong2* wr = (const ulonglong2*)(sw + j * 32);
                ulonglong2 w0 = wr[0], w1 = wr[1], w2 = wr[2], w3 = wr[3];
                ulonglong2 w4 = wr[4], w5 = wr[5], w6 = wr[6], w7 = wr[7];
                u64 a0 = mul2(h2[0], w0.x);
                u64 a1 = mul2(h2[1], w0.y);
                a0 = fma2(h2[2],  w1.x, a0);  a1 = fma2(h2[3],  w1.y, a1);
                a0 = fma2(h2[4],  w2.x, a0);  a1 = fma2(h2[5],  w2.y, a1);
                a0 = fma2(h2[6],  w3.x, a0);  a1 = fma2(h2[7],  w3.y, a1);
                a0 = fma2(h2[8],  w4.x, a0);  a1 = fma2(h2[9],  w4.y, a1);
                a0 = fma2(h2[10], w5.x, a0);  a1 = fma2(h2[11], w5.y, a1);
                a0 = fma2(h2[12], w6.x, a0);  a1 = fma2(h2[13], w6.y, a1);
                a0 = fma2(h2[14], w7.x, a0);  a1 = fma2(h2[15], w7.y, a1);
                float2 p = unpk(add2(a0, a1));
                so[tid * TS + j] = (p.x + p.y + sw[1024 + j]) * scl;
            }
        } else {
            #pragma unroll 4
            for (int j = 0; j < 32; j++)
                so[tid * TS + j] = sw[1024 + j] * scl;  // tail Q row; K/V unread
        }
        __syncthreads();

        if (mtx == 0) {
            // Q: tile-SoA [bh][qt][qq][128] float4
            float4* Qd = (float4*)g_Qt;
            #pragma unroll
            for (int r = 0; r < 8; r++) {
                int i = tid + r * 256;          // 2048 float4
                int tok = i & 255, rest = i >> 8;
                int hh = rest >> 2, qq = rest & 3;
                int ss = s0 + tok;
                int qt = ss >> 7, tk = ss & 127;
                Qd[(((b * 2 + hh) * NQT_MAX + qt) * 4 + qq) * 128 + tk] =
                    *(const float4*)(so + tok * TS + hh * 16 + qq * 4);
            }
        } else {
            float4* outp = (float4*)((mtx == 1) ? g_K : g_V);
            #pragma unroll
            for (int r = 0; r < 8; r++) {
                int i = tid + r * 256;
                int hh = i >> 10, low = i & 1023;   // low = tok*4+qq
                outp[((size_t)(b * 2 + hh) * SS + s0) * 4 + low] =
                    *(const float4*)(so + (low >> 2) * TS + hh * 16 + (low & 3) * 4);
            }
        }
        __syncthreads();
    }
}

// ---------------------------------------------------------------------------
// K2: split-K attention. Grid (B*H, NQT_MAX, NKC_MAX), 128 threads = one
//     128-query x 256-key tile; dead tiles early-exit. No-max softmax makes
//     partials plain sums -> each block writes (sum_e*v, sum_e) to its slot.
//     All global accesses coalesced (Q tiled, partials tile-SoA).
// ---------------------------------------------------------------------------
__device__ __forceinline__ void qk1(const ulonglong2* __restrict__ kp,
                                    const ulonglong2* __restrict__ vp,
                                    const u64 q[8], u64 o[8], float& l) {
    ulonglong2 k0 = kp[0], k1 = kp[1], k2 = kp[2], k3 = kp[3];
    u64 a0 = mul2(q[0], k0.x);
    u64 a1 = mul2(q[1], k0.y);
    a0 = fma2(q[2], k1.x, a0);  a1 = fma2(q[3], k1.y, a1);
    a0 = fma2(q[4], k2.x, a0);  a1 = fma2(q[5], k2.y, a1);
    a0 = fma2(q[6], k3.x, a0);  a1 = fma2(q[7], k3.y, a1);
    float2 p = unpk(add2(a0, a1));
    float e = ex2(p.x + p.y);
    l += e;
    u64 e2 = pack2(e, e);
    ulonglong2 v0 = vp[0], v1 = vp[1], v2 = vp[2], v3 = vp[3];
    o[0] = fma2(e2, v0.x, o[0]);  o[1] = fma2(e2, v0.y, o[1]);
    o[2] = fma2(e2, v1.x, o[2]);  o[3] = fma2(e2, v1.y, o[3]);
    o[4] = fma2(e2, v2.x, o[4]);  o[5] = fma2(e2, v2.y, o[5]);
    o[6] = fma2(e2, v3.x, o[6]);  o[7] = fma2(e2, v3.y, o[7]);
}

__global__ void __launch_bounds__(128) attn_kernel() {
    __shared__ __align__(16) float sK[KC * DH];   // 16 KB
    __shared__ __align__(16) float sV[KC * DH];   // 16 KB

    int bh = blockIdx.x, qt = blockIdx.y, kc = blockIdx.z;
    int b  = bh >> 1;
    int tid = threadIdx.x;
    int Lb = g_Lb[b];
    int nqt = (Lb >> 7) + 1;             // query tiles cover [0, Lb] inclusive
    int nkc = (Lb + KC - 1) >> 8;        // key chunks over [0, Lb)
    if (qt >= nqt || kc >= nkc) return;

    int k0 = kc << 8;
    int nk = min(KC, Lb - k0);

    // stage K/V chunk (coalesced float4)
    const float4* Kg = (const float4*)(g_K + ((size_t)bh * SS + k0) * DH);
    const float4* Vg = (const float4*)(g_V + ((size_t)bh * SS + k0) * DH);
    int nf = nk * 4;
    for (int i = tid; i < nf; i += 128) {
        ((float4*)sK)[i] = Kg[i];
        ((float4*)sV)[i] = Vg[i];
    }
    __syncthreads();

    // coalesced Q load from tile-SoA planes
    u64 q[8], o[8];
    {
        const float4* Qs = (const float4*)g_Qt + ((size_t)(bh * NQT_MAX + qt) * 4) * 128;
        #pragma unroll
        for (int j = 0; j < 4; j++) {
            float4 f = Qs[j * 128 + tid];
            q[2 * j]     = pack2(f.x, f.y);
            q[2 * j + 1] = pack2(f.z, f.w);
        }
    }
    #pragma unroll
    for (int j = 0; j < 8; j++) o[j] = 0ull;
    float l = 0.f;

    const u64* sKu = (const u64*)sK;
    const u64* sVu = (const u64*)sV;
    if (nk == KC) {
        #pragma unroll 2
        for (int k = 0; k < KC; k++)
            qk1((const ulonglong2*)(sKu + k * 8), (const ulonglong2*)(sVu + k * 8), q, o, l);
    } else {
        for (int k = 0; k < nk; k++)
            qk1((const ulonglong2*)(sKu + k * 8), (const ulonglong2*)(sVu + k * 8), q, o, l);
    }

    // coalesced partial write (tile-SoA planes, deterministic slot)
    size_t slot = ((size_t)(bh * NKC_MAX + kc) * NQT_MAX + qt);
    float4* Po = (float4*)g_Po + slot * 4 * 128;
    #pragma unroll
    for (int j = 0; j < 4; j++) {
        float2 pa = unpk(o[2 * j]), pb = unpk(o[2 * j + 1]);
        Po[j * 128 + tid] = make_float4(pa.x, pa.y, pb.x, pb.y);
    }
    g_Pl[slot * 128 + tid] = l;
}

// ---------------------------------------------------------------------------
// K3: finish = reduce partials + normalize + output GEMM, fused.
//     Block = 256 threads = 128 tokens (2 threads/token, one per head).
//     Each half sums its head's <=4 partials (coalesced), normalizes by its
//     own l, exchanges halves via smem, computes 14 outputs full-width.
//     Tail tokens (s >= qlim) remap to representative row (Lb>>7, Lb&127).
// ---------------------------------------------------------------------------
__global__ void __launch_bounds__(256) finish_kernel(float* __restrict__ out) {
    __shared__ __align__(16) float swc[VV * DD];
    __shared__ float sbc[VV];
    __shared__ __align__(16) float stok[128 * TS];
    __shared__ __align__(16) float sout[128 * VV];

    int tid = threadIdx.x;
    for (int i = tid; i < VV * DD; i += 256) swc[i] = g_wc[i];
    if (tid < VV) sbc[tid] = g_bc[tid];

    int t0 = blockIdx.x * 128;
    int b  = t0 >> 10, s0 = t0 & 1023;
    int qt = s0 >> 7;
    int Lb = g_Lb[b];
    int nkc  = (Lb + KC - 1) >> 8;
    int qlim = ((Lb >> 7) + 1) << 7;

    int tok = tid >> 1, half = tid & 1;
    int bh  = b * 2 + half;
    int s   = s0 + tok;
    int qt_e, tk_e;
    if (s < qlim) { qt_e = qt;      tk_e = tok; }
    else          { qt_e = Lb >> 7; tk_e = Lb & 127; }

    // sum partials for this (token, head) -- coalesced within j-planes
    float l = 0.f;
    float4 o0 = make_float4(0, 0, 0, 0), o1 = o0, o2 = o0, o3 = o0;
    #pragma unroll 4
    for (int kc = 0; kc < nkc; kc++) {
        size_t slot = ((size_t)(bh * NKC_MAX + kc) * NQT_MAX + qt_e);
        const float4* Po = (const float4*)g_Po + slot * 4 * 128;
        float4 t0v = Po[0 * 128 + tk_e], t1v = Po[1 * 128 + tk_e];
        float4 t2v = Po[2 * 128 + tk_e], t3v = Po[3 * 128 + tk_e];
        o0.x += t0v.x; o0.y += t0v.y; o0.z += t0v.z; o0.w += t0v.w;
        o1.x += t1v.x; o1.y += t1v.y; o1.z += t1v.z; o1.w += t1v.w;
        o2.x += t2v.x; o2.y += t2v.y; o2.z += t2v.z; o2.w += t2v.w;
        o3.x += t3v.x; o3.y += t3v.y; o3.z += t3v.z; o3.w += t3v.w;
        l += g_Pl[slot * 128 + tk_e];
    }
    float inv = 1.f / l;
    float* dst = stok + tok * TS + half * 16;
    *(float4*)(dst + 0)  = make_float4(o0.x * inv, o0.y * inv, o0.z * inv, o0.w * inv);
    *(float4*)(dst + 4)  = make_float4(o1.x * inv, o1.y * inv, o1.z * inv, o1.w * inv);
    *(float4*)(dst + 8)  = make_float4(o2.x * inv, o2.y * inv, o2.z * inv, o2.w * inv);
    *(float4*)(dst + 12) = make_float4(o3.x * inv, o3.y * inv, o3.z * inv, o3.w * inv);
    __syncthreads();

    // output GEMM: each half computes 14 full-width outputs
    u64 o2r[16];
    const u64* src = (const u64*)(stok + tok * TS);
    #pragma unroll
    for (int j = 0; j < 16; j++) o2r[j] = src[j];

    #pragma unroll 2
    for (int vi = 0; vi < 14; vi++) {
        int v = half * 14 + vi;
        const ulonglong2* wr = (const ulonglong2*)(swc + v * 32);
        ulonglong2 w0 = wr[0], w1 = wr[1], w2 = wr[2], w3 = wr[3];
        ulonglong2 w4 = wr[4], w5 = wr[5], w6 = wr[6], w7 = wr[7];
        u64 a0 = mul2(o2r[0], w0.x);
        u64 a1 = mul2(o2r[1], w0.y);
        a0 = fma2(o2r[2],  w1.x, a0);  a1 = fma2(o2r[3],  w1.y, a1);
        a0 = fma2(o2r[4],  w2.x, a0);  a1 = fma2(o2r[5],  w2.y, a1);
        a0 = fma2(o2r[6],  w3.x, a0);  a1 = fma2(o2r[7],  w3.y, a1);
        a0 = fma2(o2r[8],  w4.x, a0);  a1 = fma2(o2r[9],  w4.y, a1);
        a0 = fma2(o2r[10], w5.x, a0);  a1 = fma2(o2r[11], w5.y, a1);
        a0 = fma2(o2r[12], w6.x, a0);  a1 = fma2(o2r[13], w6.y, a1);
        a0 = fma2(o2r[14], w7.x, a0);  a1 = fma2(o2r[15], w7.y, a1);
        float2 p = unpk(add2(a0, a1));
        sout[tok * VV + v] = p.x + p.y + sbc[v];
    }
    __syncthreads();

    // coalesced float4 store (128*28 = 3584 floats = 896 float4)
    float4* op = (float4*)(out + (size_t)t0 * VV);
    const float4* sp = (const float4*)sout;
    #pragma unroll
    for (int r = 0; r < 4; r++) {
        int i = tid + r * 256;
        if (i < 896) op[i] = sp[i];
    }
}

// ---------------------------------------------------------------------------
extern "C" void kernel_launch(void* const* d_in, const int* in_sizes, int n_in,
                              void* d_out, int out_size) {
    const int*   x    = (const int*)  d_in[0];
    const float* mask = (const float*)d_in[1];
    const float* emb  = (const float*)d_in[2];
    const float* pe   = (const float*)d_in[3];
    const float* wq   = (const float*)d_in[4];
    const float* bq   = (const float*)d_in[5];
    const float* wk   = (const float*)d_in[6];
    const float* bk   = (const float*)d_in[7];
    const float* wv   = (const float*)d_in[8];
    const float* bv   = (const float*)d_in[9];
    const float* wo   = (const float*)d_in[10];
    const float* bo   = (const float*)d_in[11];
    const float* wfc  = (const float*)d_in[12];
    const float* bfc  = (const float*)d_in[13];
    float* out = (float*)d_out;

    prep_kernel<<<BB + 1, 256>>>(mask, wo, bo, wfc, bfc);
    qkv_kernel<<<(BB * SS) / 256, 256>>>(x, emb, pe, wq, bq, wk, bk, wv, bv);
    attn_kernel<<<dim3(BB * HH, NQT_MAX, NKC_MAX), 128>>>();
    finish_kernel<<<(BB * SS) / 128, 256>>>(out);
}

// round 15
// speedup vs baseline: 1.7027x; 1.0440x over previous
#include <cuda_runtime.h>

// Problem constants (fixed by the reference setup)
#define BB 64
#define SS 1024
#define DD 32
#define HH 2
#define DH 16
#define VV 28
#define LOG2E 1.44269504088896340736f
#define KC 256      // keys per split-K chunk
#define NKC_MAX 4   // max key chunks  (SS/KC)
#define NQT_MAX 8   // max 128-query tiles (SS/128)
#define NQP_MAX 4   // max 256-query tiles (SS/256)
#define TS 36       // token stage stride in floats (multiple of 4 -> aligned)

#define NQ (BB * HH * SS * DH)

typedef unsigned long long u64;

// Scratch (no allocations allowed -> __device__ globals), 16B-aligned
// Q in tile-SoA layout: [bh][qt][j:4][128] float4 planes (thread-contiguous)
__device__ __align__(16) float g_Qt[NQ];
__device__ __align__(16) float g_K[NQ];     // row-major [bh][s][16]
__device__ __align__(16) float g_V[NQ];
// split-K partials, tile-SoA: [bh][kc][qt][j:4][128] float4 + [bh][kc][qt][128]
__device__ __align__(16) float g_Po[(size_t)BB * HH * NKC_MAX * NQT_MAX * 128 * DH];
__device__ __align__(16) float g_Pl[(size_t)BB * HH * NKC_MAX * NQT_MAX * 128];
__device__ int   g_Lb[BB];
__device__ __align__(16) float g_wc[VV * DD];
__device__ float g_bc[VV];

// ---------------------------------------------------------------------------
// Packed f32x2 + misc PTX helpers
// ---------------------------------------------------------------------------
__device__ __forceinline__ u64 fma2(u64 a, u64 b, u64 c) {
    u64 d; asm("fma.rn.f32x2 %0,%1,%2,%3;" : "=l"(d) : "l"(a), "l"(b), "l"(c));
    return d;
}
__device__ __forceinline__ u64 mul2(u64 a, u64 b) {
    u64 d; asm("mul.rn.f32x2 %0,%1,%2;" : "=l"(d) : "l"(a), "l"(b));
    return d;
}
__device__ __forceinline__ u64 add2(u64 a, u64 b) {
    u64 d; asm("add.rn.f32x2 %0,%1,%2;" : "=l"(d) : "l"(a), "l"(b));
    return d;
}
__device__ __forceinline__ u64 pack2(float x, float y) {
    u64 r; asm("mov.b64 %0,{%1,%2};" : "=l"(r) : "f"(x), "f"(y));
    return r;
}
__device__ __forceinline__ float2 unpk(u64 v) {
    float2 r; asm("mov.b64 {%0,%1},%2;" : "=f"(r.x), "=f"(r.y) : "l"(v));
    return r;
}
__device__ __forceinline__ float ex2(float x) {
    float r; asm("ex2.approx.f32 %0,%1;" : "=f"(r) : "f"(x));
    return r;
}

// ---------------------------------------------------------------------------
// K0: per-batch prefix length Lb + combined output weights wc = w_fc @ wo
// ---------------------------------------------------------------------------
__global__ void prep_kernel(const float* __restrict__ mask,
                            const float* __restrict__ wo,
                            const float* __restrict__ bo,
                            const float* __restrict__ wfc,
                            const float* __restrict__ bfc) {
    int tid = threadIdx.x;
    int bb  = blockIdx.x;
    if (bb < BB) {
        __shared__ int smax[256];
        int mx = -1;
        const float* mp = mask + bb * SS;
        for (int s = tid; s < SS; s += 256)
            if (mp[s] > 0.f) mx = max(mx, s);
        smax[tid] = mx;
        __syncthreads();
        for (int off = 128; off > 0; off >>= 1) {
            if (tid < off) smax[tid] = max(smax[tid], smax[tid + off]);
            __syncthreads();
        }
        if (tid == 0) g_Lb[bb] = min(smax[0] + 4, SS - 1);
    } else {
        for (int e = tid; e < VV * DD; e += 256) {
            int v = e >> 5, d = e & 31;
            float acc = 0.f;
            #pragma unroll
            for (int t = 0; t < 32; t++)
                acc += wfc[v * 32 + t] * wo[t * 32 + d];
            g_wc[e] = acc;
        }
        if (tid < VV) {
            float acc = bfc[tid];
            #pragma unroll
            for (int t = 0; t < 32; t++)
                acc += wfc[tid * 32 + t] * bo[t];
            g_bc[tid] = acc;
        }
    }
}

// ---------------------------------------------------------------------------
// K1: QKV projections, 256 tokens/block (one batch b). One weight matrix
//     staged in smem at a time. Outputs staged at stride TS=36, then written
//     COALESCED: Q tile-SoA, K/V row-major. Q pre-scaled 0.25*log2e.
// ---------------------------------------------------------------------------
__global__ void __launch_bounds__(256) qkv_kernel(
    const int* __restrict__ x,  const float* __restrict__ emb,
    const float* __restrict__ pe,
    const float* __restrict__ wq, const float* __restrict__ bq,
    const float* __restrict__ wk, const float* __restrict__ bk,
    const float* __restrict__ wv, const float* __restrict__ bv) {

    __shared__ __align__(16) float sw[1024 + 32];
    __shared__ __align__(16) float so[256 * TS];     // 36 KB
    int tid = threadIdx.x;

    int t0 = blockIdx.x * 256;
    int b  = t0 >> 10, s0 = t0 & 1023;
    int s  = s0 + tid;
    int Lb = g_Lb[b];
    const float QSCL = 0.25f * LOG2E;
    bool live = (s < Lb);

    u64 h2[16];
    if (live) {
        int xid = x[t0 + tid];
        const float4* ep = (const float4*)(emb + xid * 32);
        const float4* pp = (const float4*)(pe + s * 32);
        #pragma unroll
        for (int j = 0; j < 8; j++) {
            float4 e4 = ep[j], p4 = pp[j];
            h2[2 * j]     = pack2(e4.x + p4.x, e4.y + p4.y);
            h2[2 * j + 1] = pack2(e4.z + p4.z, e4.w + p4.w);
        }
    }

    #pragma unroll
    for (int mtx = 0; mtx < 3; mtx++) {
        const float* wg = (mtx == 0) ? wq : ((mtx == 1) ? wk : wv);
        const float* bg = (mtx == 0) ? bq : ((mtx == 1) ? bk : bv);
        float scl = (mtx == 0) ? QSCL : 1.0f;

        for (int i = tid; i < 1024; i += 256) sw[i] = wg[i];
        if (tid < 32) sw[1024 + tid] = bg[tid];
        __syncthreads();

        if (live) {
            #pragma unroll 4
            for (int j = 0; j < 32; j++) {
                const ulonglong2* wr = (const ulonglong2*)(sw + j * 32);
                ulonglong2 w0 = wr[0], w1 = wr[1], w2 = wr[2], w3 = wr[3];
                ulonglong2 w4 = wr[4], w5 = wr[5], w6 = wr[6], w7 = wr[7];
                u64 a0 = mul2(h2[0], w0.x);
                u64 a1 = mul2(h2[1], w0.y);
                a0 = fma2(h2[2],  w1.x, a0);  a1 = fma2(h2[3],  w1.y, a1);
                a0 = fma2(h2[4],  w2.x, a0);  a1 = fma2(h2[5],  w2.y, a1);
                a0 = fma2(h2[6],  w3.x, a0);  a1 = fma2(h2[7],  w3.y, a1);
                a0 = fma2(h2[8],  w4.x, a0);  a1 = fma2(h2[9],  w4.y, a1);
                a0 = fma2(h2[10], w5.x, a0);  a1 = fma2(h2[11], w5.y, a1);
                a0 = fma2(h2[12], w6.x, a0);  a1 = fma2(h2[13], w6.y, a1);
                a0 = fma2(h2[14], w7.x, a0);  a1 = fma2(h2[15], w7.y, a1);
                float2 p = unpk(add2(a0, a1));
                so[tid * TS + j] = (p.x + p.y + sw[1024 + j]) * scl;
            }
        } else {
            #pragma unroll 4
            for (int j = 0; j < 32; j++)
                so[tid * TS + j] = sw[1024 + j] * scl;  // tail Q row; K/V unread
        }
        __syncthreads();

        if (mtx == 0) {
            // Q: tile-SoA [bh][qt][qq][128] float4
            float4* Qd = (float4*)g_Qt;
            #pragma unroll
            for (int r = 0; r < 8; r++) {
                int i = tid + r * 256;          // 2048 float4
                int tok = i & 255, rest = i >> 8;
                int hh = rest >> 2, qq = rest & 3;
                int ss = s0 + tok;
                int qt = ss >> 7, tk = ss & 127;
                Qd[(((b * 2 + hh) * NQT_MAX + qt) * 4 + qq) * 128 + tk] =
                    *(const float4*)(so + tok * TS + hh * 16 + qq * 4);
            }
        } else {
            float4* outp = (float4*)((mtx == 1) ? g_K : g_V);
            #pragma unroll
            for (int r = 0; r < 8; r++) {
                int i = tid + r * 256;
                int hh = i >> 10, low = i & 1023;   // low = tok*4+qq
                outp[((size_t)(b * 2 + hh) * SS + s0) * 4 + low] =
                    *(const float4*)(so + (low >> 2) * TS + hh * 16 + (low & 3) * 4);
            }
        }
        __syncthreads();
    }
}

// ---------------------------------------------------------------------------
// K2: split-K attention, 2 queries per thread. Grid (B*H, NQP_MAX, NKC_MAX),
//     128 threads = one 256-query x 256-key tile; dead tiles early-exit.
//     K/V staged once per 256 queries (LDS amortized across both queries).
//     Partials written per-128 qt plane (finish_kernel unchanged).
// ---------------------------------------------------------------------------
__device__ __forceinline__ void qk2(const ulonglong2* __restrict__ kp,
                                    const ulonglong2* __restrict__ vp,
                                    const u64 qa[8], const u64 qb[8],
                                    u64 oa[8], u64 ob[8],
                                    float& la, float& lb) {
    ulonglong2 k0 = kp[0], k1 = kp[1], k2 = kp[2], k3 = kp[3];
    u64 a = mul2(qa[0], k0.x);
    u64 b = mul2(qb[0], k0.x);
    a = fma2(qa[1], k0.y, a);  b = fma2(qb[1], k0.y, b);
    a = fma2(qa[2], k1.x, a);  b = fma2(qb[2], k1.x, b);
    a = fma2(qa[3], k1.y, a);  b = fma2(qb[3], k1.y, b);
    a = fma2(qa[4], k2.x, a);  b = fma2(qb[4], k2.x, b);
    a = fma2(qa[5], k2.y, a);  b = fma2(qb[5], k2.y, b);
    a = fma2(qa[6], k3.x, a);  b = fma2(qb[6], k3.x, b);
    a = fma2(qa[7], k3.y, a);  b = fma2(qb[7], k3.y, b);
    float2 pa = unpk(a), pb = unpk(b);
    float ea = ex2(pa.x + pa.y);
    float eb = ex2(pb.x + pb.y);
    la += ea;  lb += eb;
    u64 ea2 = pack2(ea, ea), eb2 = pack2(eb, eb);
    ulonglong2 v0 = vp[0], v1 = vp[1], v2 = vp[2], v3 = vp[3];
    oa[0] = fma2(ea2, v0.x, oa[0]);  ob[0] = fma2(eb2, v0.x, ob[0]);
    oa[1] = fma2(ea2, v0.y, oa[1]);  ob[1] = fma2(eb2, v0.y, ob[1]);
    oa[2] = fma2(ea2, v1.x, oa[2]);  ob[2] = fma2(eb2, v1.x, ob[2]);
    oa[3] = fma2(ea2, v1.y, oa[3]);  ob[3] = fma2(eb2, v1.y, ob[3]);
    oa[4] = fma2(ea2, v2.x, oa[4]);  ob[4] = fma2(eb2, v2.x, ob[4]);
    oa[5] = fma2(ea2, v2.y, oa[5]);  ob[5] = fma2(eb2, v2.y, ob[5]);
    oa[6] = fma2(ea2, v3.x, oa[6]);  ob[6] = fma2(eb2, v3.x, ob[6]);
    oa[7] = fma2(ea2, v3.y, oa[7]);  ob[7] = fma2(eb2, v3.y, ob[7]);
}

__global__ void __launch_bounds__(128) attn_kernel() {
    __shared__ __align__(16) float sK[KC * DH];   // 16 KB
    __shared__ __align__(16) float sV[KC * DH];   // 16 KB

    int bh = blockIdx.x, qp = blockIdx.y, kc = blockIdx.z;
    int b  = bh >> 1;
    int tid = threadIdx.x;
    int Lb = g_Lb[b];
    int nqp = (Lb >> 8) + 1;             // 256-query tiles cover [0, Lb]
    int nkc = (Lb + KC - 1) >> 8;        // key chunks over [0, Lb)
    if (qp >= nqp || kc >= nkc) return;

    int k0 = kc << 8;
    int nk = min(KC, Lb - k0);

    // stage K/V chunk (coalesced float4)
    const float4* Kg = (const float4*)(g_K + ((size_t)bh * SS + k0) * DH);
    const float4* Vg = (const float4*)(g_V + ((size_t)bh * SS + k0) * DH);
    int nf = nk * 4;
    for (int i = tid; i < nf; i += 128) {
        ((float4*)sK)[i] = Kg[i];
        ((float4*)sV)[i] = Vg[i];
    }
    __syncthreads();

    // two 128-query planes of this 256-query tile (coalesced tile-SoA loads)
    int qt0 = qp * 2;
    u64 qa[8], qb[8], oa[8], ob[8];
    {
        const float4* Qa = (const float4*)g_Qt + ((size_t)(bh * NQT_MAX + qt0) * 4) * 128;
        const float4* Qb = Qa + 4 * 128;
        #pragma unroll
        for (int j = 0; j < 4; j++) {
            float4 fa = Qa[j * 128 + tid];
            float4 fb = Qb[j * 128 + tid];
            qa[2 * j]     = pack2(fa.x, fa.y);
            qa[2 * j + 1] = pack2(fa.z, fa.w);
            qb[2 * j]     = pack2(fb.x, fb.y);
            qb[2 * j + 1] = pack2(fb.z, fb.w);
        }
    }
    #pragma unroll
    for (int j = 0; j < 8; j++) { oa[j] = 0ull; ob[j] = 0ull; }
    float la = 0.f, lb = 0.f;

    const u64* sKu = (const u64*)sK;
    const u64* sVu = (const u64*)sV;
    if (nk == KC) {
        #pragma unroll 2
        for (int k = 0; k < KC; k++)
            qk2((const ulonglong2*)(sKu + k * 8), (const ulonglong2*)(sVu + k * 8),
                qa, qb, oa, ob, la, lb);
    } else {
        for (int k = 0; k < nk; k++)
            qk2((const ulonglong2*)(sKu + k * 8), (const ulonglong2*)(sVu + k * 8),
                qa, qb, oa, ob, la, lb);
    }

    // coalesced partial writes (two 128-query qt planes)
    size_t slotA = ((size_t)(bh * NKC_MAX + kc) * NQT_MAX + qt0);
    float4* PoA = (float4*)g_Po + slotA * 4 * 128;
    float4* PoB = PoA + 4 * 128;
    #pragma unroll
    for (int j = 0; j < 4; j++) {
        float2 pa0 = unpk(oa[2 * j]), pa1 = unpk(oa[2 * j + 1]);
        float2 pb0 = unpk(ob[2 * j]), pb1 = unpk(ob[2 * j + 1]);
        PoA[j * 128 + tid] = make_float4(pa0.x, pa0.y, pa1.x, pa1.y);
        PoB[j * 128 + tid] = make_float4(pb0.x, pb0.y, pb1.x, pb1.y);
    }
    g_Pl[slotA * 128 + tid]       = la;
    g_Pl[(slotA + 1) * 128 + tid] = lb;
}

// ---------------------------------------------------------------------------
// K3: finish = reduce partials + normalize + output GEMM, fused.
//     Block = 256 threads = 128 tokens (2 threads/token, one per head).
//     Tail tokens (s >= qlim) remap to representative row (Lb>>7, Lb&127).
// ---------------------------------------------------------------------------
__global__ void __launch_bounds__(256) finish_kernel(float* __restrict__ out) {
    __shared__ __align__(16) float swc[VV * DD];
    __shared__ float sbc[VV];
    __shared__ __align__(16) float stok[128 * TS];
    __shared__ __align__(16) float sout[128 * VV];

    int tid = threadIdx.x;
    for (int i = tid; i < VV * DD; i += 256) swc[i] = g_wc[i];
    if (tid < VV) sbc[tid] = g_bc[tid];

    int t0 = blockIdx.x * 128;
    int b  = t0 >> 10, s0 = t0 & 1023;
    int qt = s0 >> 7;
    int Lb = g_Lb[b];
    int nkc  = (Lb + KC - 1) >> 8;
    int qlim = ((Lb >> 7) + 1) << 7;

    int tok = tid >> 1, half = tid & 1;
    int bh  = b * 2 + half;
    int s   = s0 + tok;
    int qt_e, tk_e;
    if (s < qlim) { qt_e = qt;      tk_e = tok; }
    else          { qt_e = Lb >> 7; tk_e = Lb & 127; }

    // sum partials for this (token, head) -- coalesced within j-planes
    float l = 0.f;
    float4 o0 = make_float4(0, 0, 0, 0), o1 = o0, o2 = o0, o3 = o0;
    #pragma unroll 4
    for (int kc = 0; kc < nkc; kc++) {
        size_t slot = ((size_t)(bh * NKC_MAX + kc) * NQT_MAX + qt_e);
        const float4* Po = (const float4*)g_Po + slot * 4 * 128;
        float4 t0v = Po[0 * 128 + tk_e], t1v = Po[1 * 128 + tk_e];
        float4 t2v = Po[2 * 128 + tk_e], t3v = Po[3 * 128 + tk_e];
        o0.x += t0v.x; o0.y += t0v.y; o0.z += t0v.z; o0.w += t0v.w;
        o1.x += t1v.x; o1.y += t1v.y; o1.z += t1v.z; o1.w += t1v.w;
        o2.x += t2v.x; o2.y += t2v.y; o2.z += t2v.z; o2.w += t2v.w;
        o3.x += t3v.x; o3.y += t3v.y; o3.z += t3v.z; o3.w += t3v.w;
        l += g_Pl[slot * 128 + tk_e];
    }
    float inv = 1.f / l;
    float* dst = stok + tok * TS + half * 16;
    *(float4*)(dst + 0)  = make_float4(o0.x * inv, o0.y * inv, o0.z * inv, o0.w * inv);
    *(float4*)(dst + 4)  = make_float4(o1.x * inv, o1.y * inv, o1.z * inv, o1.w * inv);
    *(float4*)(dst + 8)  = make_float4(o2.x * inv, o2.y * inv, o2.z * inv, o2.w * inv);
    *(float4*)(dst + 12) = make_float4(o3.x * inv, o3.y * inv, o3.z * inv, o3.w * inv);
    __syncthreads();

    // output GEMM: each half computes 14 full-width outputs
    u64 o2r[16];
    const u64* src = (const u64*)(stok + tok * TS);
    #pragma unroll
    for (int j = 0; j < 16; j++) o2r[j] = src[j];

    #pragma unroll 2
    for (int vi = 0; vi < 14; vi++) {
        int v = half * 14 + vi;
        const ulonglong2* wr = (const ulonglong2*)(swc + v * 32);
        ulonglong2 w0 = wr[0], w1 = wr[1], w2 = wr[2], w3 = wr[3];
        ulonglong2 w4 = wr[4], w5 = wr[5], w6 = wr[6], w7 = wr[7];
        u64 a0 = mul2(o2r[0], w0.x);
        u64 a1 = mul2(o2r[1], w0.y);
        a0 = fma2(o2r[2],  w1.x, a0);  a1 = fma2(o2r[3],  w1.y, a1);
        a0 = fma2(o2r[4],  w2.x, a0);  a1 = fma2(o2r[5],  w2.y, a1);
        a0 = fma2(o2r[6],  w3.x, a0);  a1 = fma2(o2r[7],  w3.y, a1);
        a0 = fma2(o2r[8],  w4.x, a0);  a1 = fma2(o2r[9],  w4.y, a1);
        a0 = fma2(o2r[10], w5.x, a0);  a1 = fma2(o2r[11], w5.y, a1);
        a0 = fma2(o2r[12], w6.x, a0);  a1 = fma2(o2r[13], w6.y, a1);
        a0 = fma2(o2r[14], w7.x, a0);  a1 = fma2(o2r[15], w7.y, a1);
        float2 p = unpk(add2(a0, a1));
        sout[tok * VV + v] = p.x + p.y + sbc[v];
    }
    __syncthreads();

    // coalesced float4 store (128*28 = 3584 floats = 896 float4)
    float4* op = (float4*)(out + (size_t)t0 * VV);
    const float4* sp = (const float4*)sout;
    #pragma unroll
    for (int r = 0; r < 4; r++) {
        int i = tid + r * 256;
        if (i < 896) op[i] = sp[i];
    }
}

// ---------------------------------------------------------------------------
extern "C" void kernel_launch(void* const* d_in, const int* in_sizes, int n_in,
                              void* d_out, int out_size) {
    const int*   x    = (const int*)  d_in[0];
    const float* mask = (const float*)d_in[1];
    const float* emb  = (const float*)d_in[2];
    const float* pe   = (const float*)d_in[3];
    const float* wq   = (const float*)d_in[4];
    const float* bq   = (const float*)d_in[5];
    const float* wk   = (const float*)d_in[6];
    const float* bk   = (const float*)d_in[7];
    const float* wv   = (const float*)d_in[8];
    const float* bv   = (const float*)d_in[9];
    const float* wo   = (const float*)d_in[10];
    const float* bo   = (const float*)d_in[11];
    const float* wfc  = (const float*)d_in[12];
    const float* bfc  = (const float*)d_in[13];
    float* out = (float*)d_out;

    prep_kernel<<<BB + 1, 256>>>(mask, wo, bo, wfc, bfc);
    qkv_kernel<<<(BB * SS) / 256, 256>>>(x, emb, pe, wq, bq, wk, bk, wv, bv);
    attn_kernel<<<dim3(BB * HH, NQP_MAX, NKC_MAX), 128>>>();
    finish_kernel<<<(BB * SS) / 128, 256>>>(out);
}